// round 2
// baseline (speedup 1.0000x reference)
#include <cuda_runtime.h>
#include <math.h>

// Problem constants
#define BATCH   8
#define NPB     4096
#define NPTS    (BATCH*NPB)      // 32768
#define KNN     16
#define CF      64
#define NKROWS  (NPTS*KNN)       // 524288
#define HDIM    8

// ---------------- scratch (device globals; no allocation) ----------------
__device__ float d_xq[NPTS*CF];
__device__ float d_xk[NPTS*CF];
__device__ float d_xv[NPTS*CF];
__device__ float d_sqk[NPTS];
__device__ float d_sqv[NPTS];
__device__ int   d_idxk[NKROWS];
__device__ int   d_idxv[NKROWS];
__device__ float d_h[NKROWS*3];
__device__ float d_pr[(size_t)NKROWS*CF];   // 128 MB
__device__ float d_rr[(size_t)NKROWS*CF];   // 128 MB
__device__ float d_w1[NKROWS*HDIM];
__device__ float d_part[1024*128];
// stats: [0..2] mean_h, [3..5] rstd_h, [8..71] mean_r, [72..135] rstd_r,
//        [136..143] mean_w, [144..151] rstd_w
__device__ float d_stats[160];

// ---------------- L1: q/k/v projections ----------------
__global__ __launch_bounds__(256) void qkv_kernel(
    const float* __restrict__ x,
    const float* __restrict__ wq, const float* __restrict__ bq,
    const float* __restrict__ wk, const float* __restrict__ bk,
    const float* __restrict__ wv, const float* __restrict__ bv)
{
    __shared__ float xs[16][64];
    __shared__ float ws[64][64];
    int t = threadIdx.x;
    int row = t >> 4, quad = t & 15;
    int rbase = blockIdx.x * 16;
    for (int i = t; i < 16*64; i += 256)
        xs[i>>6][i&63] = x[(size_t)(rbase + (i>>6))*64 + (i&63)];

    for (int m = 0; m < 3; ++m) {
        const float* W = (m==0) ? wq : (m==1) ? wk : wv;
        const float* Bv = (m==0) ? bq : (m==1) ? bk : bv;
        float* O = (m==0) ? d_xq : (m==1) ? d_xk : d_xv;
        __syncthreads();
        for (int i = t; i < 64*64; i += 256) ws[i>>6][i&63] = W[i];
        __syncthreads();
        float a0 = Bv[quad*4+0], a1 = Bv[quad*4+1], a2 = Bv[quad*4+2], a3 = Bv[quad*4+3];
        #pragma unroll 8
        for (int i = 0; i < 64; ++i) {
            float xv_ = xs[row][i];
            float4 w4 = *(const float4*)&ws[i][quad*4];
            a0 += xv_*w4.x; a1 += xv_*w4.y; a2 += xv_*w4.z; a3 += xv_*w4.w;
        }
        float4 o4; o4.x=a0; o4.y=a1; o4.z=a2; o4.w=a3;
        *(float4*)&O[(size_t)(rbase+row)*64 + quad*4] = o4;
    }
}

// ---------------- L1b: squared norms of xk and xv ----------------
__global__ __launch_bounds__(256) void sq_kernel()
{
    int w = threadIdx.x >> 5, l = threadIdx.x & 31;
    int row = blockIdx.x*8 + w;
    float a = d_xk[(size_t)row*64 + l], b = d_xk[(size_t)row*64 + 32 + l];
    float s = a*a + b*b;
    #pragma unroll
    for (int o = 16; o; o >>= 1) s += __shfl_xor_sync(0xffffffffu, s, o);
    if (l == 0) d_sqk[row] = s;
    a = d_xv[(size_t)row*64 + l]; b = d_xv[(size_t)row*64 + 32 + l];
    s = a*a + b*b;
    #pragma unroll
    for (int o = 16; o; o >>= 1) s += __shfl_xor_sync(0xffffffffu, s, o);
    if (l == 0) d_sqv[row] = s;
}

// ---------------- L2: fused distance + top-16 KNN ----------------
// grid (64, 8, 2): x = 64-query tile, y = batch, z = space (0:k, 1:v)
__global__ __launch_bounds__(256) void knn_kernel()
{
    const int sp = blockIdx.z;
    const float* feat  = sp ? d_xv  : d_xk;
    const float* sqA   = sp ? d_sqv : d_sqk;
    int*         outIx = sp ? d_idxv : d_idxk;
    const int batch = blockIdx.y;
    const int qbase = batch*NPB + blockIdx.x*64;

    __shared__ float smemA[64*65];   // cand tile (64x64) / dist (64x65) / mergeD (64x64)
    __shared__ float smemQ[64*64];   // query tile [feat][q] / mergeI
    __shared__ float sqQ[64];
    __shared__ float sqC[64];

    const int t  = threadIdx.x;
    const int qg = t >> 4, cg = t & 15;      // GEMM roles: 4 queries x 4 cands
    const int qs = t & 63, part = t >> 6;    // scan roles: query, 16-col slice

    // load query tile transposed: qT(k,q) = smemQ[k*64+q]
    for (int i = t; i < 64*16; i += 256) {
        int r = i >> 4, f4 = i & 15;
        float4 g = *(const float4*)&feat[(size_t)(qbase + r)*64 + f4*4];
        smemQ[(4*f4+0)*64 + r] = g.x;
        smemQ[(4*f4+1)*64 + r] = g.y;
        smemQ[(4*f4+2)*64 + r] = g.z;
        smemQ[(4*f4+3)*64 + r] = g.w;
    }
    if (t < 64) sqQ[t] = sqA[qbase + t];

    float listD[16]; int listI[16];
    #pragma unroll
    for (int e = 0; e < 16; ++e) { listD[e] = 3.4e38f; listI[e] = 0x7fffffff; }

    for (int tile = 0; tile < 64; ++tile) {
        const int cbase = batch*NPB + tile*64;
        __syncthreads();   // previous dist fully consumed before cT overwrite
        for (int i = t; i < 64*16; i += 256) {
            int r = i >> 4, f4 = i & 15;
            float4 g = *(const float4*)&feat[(size_t)(cbase + r)*64 + f4*4];
            smemA[(4*f4+0)*64 + r] = g.x;
            smemA[(4*f4+1)*64 + r] = g.y;
            smemA[(4*f4+2)*64 + r] = g.z;
            smemA[(4*f4+3)*64 + r] = g.w;
        }
        if (t < 64) sqC[t] = sqA[cbase + t];
        __syncthreads();

        float acc[4][4];
        #pragma unroll
        for (int a = 0; a < 4; ++a)
            #pragma unroll
            for (int b = 0; b < 4; ++b) acc[a][b] = 0.f;

        #pragma unroll 4
        for (int kk = 0; kk < 64; ++kk) {
            float4 qv = *(const float4*)&smemQ[kk*64 + qg*4];
            float4 cv = *(const float4*)&smemA[kk*64 + cg*4];
            acc[0][0] += qv.x*cv.x; acc[0][1] += qv.x*cv.y; acc[0][2] += qv.x*cv.z; acc[0][3] += qv.x*cv.w;
            acc[1][0] += qv.y*cv.x; acc[1][1] += qv.y*cv.y; acc[1][2] += qv.y*cv.z; acc[1][3] += qv.y*cv.w;
            acc[2][0] += qv.z*cv.x; acc[2][1] += qv.z*cv.y; acc[2][2] += qv.z*cv.z; acc[2][3] += qv.z*cv.w;
            acc[3][0] += qv.w*cv.x; acc[3][1] += qv.w*cv.y; acc[3][2] += qv.w*cv.z; acc[3][3] += qv.w*cv.w;
        }
        __syncthreads();   // all reads of cT done; reuse buffer as dist

        float sqq0 = sqQ[qg*4+0], sqq1 = sqQ[qg*4+1], sqq2 = sqQ[qg*4+2], sqq3 = sqQ[qg*4+3];
        #pragma unroll
        for (int ci = 0; ci < 4; ++ci) {
            float sc = sqC[cg*4+ci];
            smemA[(qg*4+0)*65 + cg*4+ci] = sqq0 + sc - 2.f*acc[0][ci];
            smemA[(qg*4+1)*65 + cg*4+ci] = sqq1 + sc - 2.f*acc[1][ci];
            smemA[(qg*4+2)*65 + cg*4+ci] = sqq2 + sc - 2.f*acc[2][ci];
            smemA[(qg*4+3)*65 + cg*4+ci] = sqq3 + sc - 2.f*acc[3][ci];
        }
        __syncthreads();

        // top-16 maintenance: 4 threads/query, 16 candidates each
        #pragma unroll
        for (int i = 0; i < 16; ++i) {
            int c = part*16 + i;
            float dd = smemA[qs*65 + c];
            int   ci = cbase + c;   // global index (matches jax batch-offset idx)
            if (dd < listD[15] || (dd == listD[15] && ci < listI[15])) {
                float cd = dd; int cix = ci;
                #pragma unroll
                for (int e = 0; e < 16; ++e) {
                    bool better = (cd < listD[e]) || (cd == listD[e] && cix < listI[e]);
                    float od = listD[e]; int oi = listI[e];
                    if (better) { listD[e] = cd; listI[e] = cix; cd = od; cix = oi; }
                }
            }
        }
    }
    __syncthreads();
    // merge 4 partial lists per query (qT dead -> reuse as int buffer)
    int* mI = (int*)smemQ;
    #pragma unroll
    for (int e = 0; e < 16; ++e) {
        smemA[qs*64 + part*16 + e] = listD[e];
        mI[qs*64 + part*16 + e]    = listI[e];
    }
    __syncthreads();
    if (t < 64) {
        float fD[16]; int fI[16];
        #pragma unroll
        for (int e = 0; e < 16; ++e) { fD[e] = 3.4e38f; fI[e] = 0x7fffffff; }
        for (int j = 0; j < 64; ++j) {
            float dd = smemA[t*64 + j];
            int   ci = mI[t*64 + j];
            if (dd < fD[15] || (dd == fD[15] && ci < fI[15])) {
                float cd = dd; int cix = ci;
                #pragma unroll
                for (int e = 0; e < 16; ++e) {
                    bool better = (cd < fD[e]) || (cd == fD[e] && cix < fI[e]);
                    float od = fD[e]; int oi = fI[e];
                    if (better) { fD[e] = cd; fI[e] = cix; cd = od; cix = oi; }
                }
            }
        }
        int gp = qbase + t;
        #pragma unroll
        for (int e = 0; e < 16; ++e) outIx[(size_t)gp*16 + e] = fI[e];
    }
}

// ---------------- L3: h = p_rel @ wp1 + bp1, plus partial stats (3 ch) ----------------
__global__ __launch_bounds__(256) void hstats_kernel(
    const float* __restrict__ p, const float* __restrict__ wp1, const float* __restrict__ bp1)
{
    int t = threadIdx.x;
    float w[9];
    #pragma unroll
    for (int j = 0; j < 9; ++j) w[j] = wp1[j];
    float b0 = bp1[0], b1 = bp1[1], b2 = bp1[2];
    float s0=0,s1=0,s2=0,q0=0,q1=0,q2=0;
    for (int rep = 0; rep < 4; ++rep) {
        int row = blockIdx.x*1024 + rep*256 + t;
        int n = row >> 4;
        int gi = d_idxk[row];
        float r0 = p[(size_t)gi*3+0] - p[(size_t)n*3+0];
        float r1 = p[(size_t)gi*3+1] - p[(size_t)n*3+1];
        float r2 = p[(size_t)gi*3+2] - p[(size_t)n*3+2];
        float h0 = r0*w[0] + r1*w[3] + r2*w[6] + b0;
        float h1 = r0*w[1] + r1*w[4] + r2*w[7] + b1;
        float h2 = r0*w[2] + r1*w[5] + r2*w[8] + b2;
        d_h[(size_t)row*3+0] = h0; d_h[(size_t)row*3+1] = h1; d_h[(size_t)row*3+2] = h2;
        s0 += h0; s1 += h1; s2 += h2;
        q0 += h0*h0; q1 += h1*h1; q2 += h2*h2;
    }
    __shared__ float red[6][256];
    red[0][t]=s0; red[1][t]=s1; red[2][t]=s2; red[3][t]=q0; red[4][t]=q1; red[5][t]=q2;
    __syncthreads();
    for (int st = 128; st; st >>= 1) {
        if (t < st) {
            #pragma unroll
            for (int e = 0; e < 6; ++e) red[e][t] += red[e][t+st];
        }
        __syncthreads();
    }
    if (t < 6) d_part[blockIdx.x*6 + t] = red[t][0];
}

// ---------------- generic deterministic finalize (mean / rstd) ----------------
__global__ __launch_bounds__(256) void finalize_kernel(int nch, int nblocks, int statOff)
{
    __shared__ double sh[512];
    int t = threadIdx.x;
    int nsl = 256 / nch;
    int c = t % nch, sl = t / nch;
    double s = 0.0, q = 0.0;
    if (sl < nsl) {
        for (int b = sl; b < nblocks; b += nsl) {
            s += (double)d_part[(size_t)b*2*nch + c];
            q += (double)d_part[(size_t)b*2*nch + nch + c];
        }
    }
    sh[t] = s; sh[256 + t] = q;
    __syncthreads();
    if (t < nch) {
        double S = 0.0, Q = 0.0;
        for (int s2 = 0; s2 < nsl; ++s2) { S += sh[s2*nch + t]; Q += sh[256 + s2*nch + t]; }
        double cnt = (double)NKROWS;
        double m = S / cnt;
        double v = Q / cnt - m*m;
        d_stats[statOff + t]        = (float)m;
        d_stats[statOff + nch + t]  = (float)(1.0 / sqrt(v + 1e-5));
    }
}

// ---------------- L5: p_r and r, plus partial stats over r (64 ch) ----------------
__global__ __launch_bounds__(256) void pr_r_kernel(
    const float* __restrict__ gp, const float* __restrict__ btp,
    const float* __restrict__ wp2, const float* __restrict__ bp2)
{
    int t = threadIdx.x;
    int rl = t >> 4, quad = t & 15;
    __shared__ float wp2s[3][64];
    __shared__ float bp2s[64];
    __shared__ float bnp[12];
    if (t < 192) wp2s[t/64][t%64] = wp2[t];
    if (t < 64)  bp2s[t] = bp2[t];
    if (t < 6)   bnp[t] = d_stats[t];
    if (t >= 6 && t < 9)   bnp[t] = gp[t-6];
    if (t >= 9 && t < 12)  bnp[t] = btp[t-9];
    __syncthreads();

    float4 w0 = *(const float4*)&wp2s[0][quad*4];
    float4 w1 = *(const float4*)&wp2s[1][quad*4];
    float4 w2 = *(const float4*)&wp2s[2][quad*4];
    float4 bp4 = *(const float4*)&bp2s[quad*4];
    float sx=0,sy=0,sz=0,sw=0, qx=0,qy=0,qz=0,qw=0;

    for (int it = 0; it < 32; ++it) {
        size_t row = (size_t)blockIdx.x*512 + it*16 + rl;
        float h0 = d_h[row*3+0], h1 = d_h[row*3+1], h2 = d_h[row*3+2];
        h0 = fmaxf((h0 - bnp[0])*bnp[3]*bnp[6] + bnp[9],  0.f);
        h1 = fmaxf((h1 - bnp[1])*bnp[4]*bnp[7] + bnp[10], 0.f);
        h2 = fmaxf((h2 - bnp[2])*bnp[5]*bnp[8] + bnp[11], 0.f);
        float4 pr;
        pr.x = bp4.x + h0*w0.x + h1*w1.x + h2*w2.x;
        pr.y = bp4.y + h0*w0.y + h1*w1.y + h2*w2.y;
        pr.z = bp4.z + h0*w0.z + h1*w1.z + h2*w2.z;
        pr.w = bp4.w + h0*w0.w + h1*w1.w + h2*w2.w;
        int n  = (int)(row >> 4);
        int gi = d_idxk[row];
        float4 xk4 = *(const float4*)&d_xk[(size_t)gi*64 + quad*4];
        float4 xq4 = *(const float4*)&d_xq[(size_t)n*64 + quad*4];
        float4 r4;
        r4.x = xk4.x - xq4.x + pr.x;
        r4.y = xk4.y - xq4.y + pr.y;
        r4.z = xk4.z - xq4.z + pr.z;
        r4.w = xk4.w - xq4.w + pr.w;
        *(float4*)&d_pr[row*64 + quad*4] = pr;
        *(float4*)&d_rr[row*64 + quad*4] = r4;
        sx += r4.x; sy += r4.y; sz += r4.z; sw += r4.w;
        qx += r4.x*r4.x; qy += r4.y*r4.y; qz += r4.z*r4.z; qw += r4.w*r4.w;
    }
    __shared__ float red[16][16][8];
    red[rl][quad][0]=sx; red[rl][quad][1]=sy; red[rl][quad][2]=sz; red[rl][quad][3]=sw;
    red[rl][quad][4]=qx; red[rl][quad][5]=qy; red[rl][quad][6]=qz; red[rl][quad][7]=qw;
    __syncthreads();
    for (int st = 8; st; st >>= 1) {
        if (rl < st) {
            #pragma unroll
            for (int e = 0; e < 8; ++e) red[rl][quad][e] += red[rl+st][quad][e];
        }
        __syncthreads();
    }
    if (rl == 0) {
        #pragma unroll
        for (int j = 0; j < 4; ++j) {
            d_part[(size_t)blockIdx.x*128 + quad*4 + j]      = red[0][quad][j];
            d_part[(size_t)blockIdx.x*128 + 64 + quad*4 + j] = red[0][quad][4+j];
        }
    }
}

// ---------------- L7: w1 = relu(bn1(r)) @ ww1 + bw1, plus partial stats (8 ch) ----------------
__global__ __launch_bounds__(256) void w1_kernel(
    const float* __restrict__ g1, const float* __restrict__ bt1,
    const float* __restrict__ ww1, const float* __restrict__ bw1)
{
    int t = threadIdx.x;
    int rw = t >> 3, j = t & 7;
    __shared__ float rS[32][65];
    __shared__ float ww1s[64][8];
    __shared__ float bn1[256];
    __shared__ float bw1s[8];
    if (t < 64) {
        bn1[t]       = d_stats[8 + t];
        bn1[64 + t]  = d_stats[72 + t];
        bn1[128 + t] = g1[t];
        bn1[192 + t] = bt1[t];
    }
    if (t < 8) bw1s[t] = bw1[t];
    for (int i = t; i < 512; i += 256) ww1s[i>>3][i&7] = ww1[i];
    __syncthreads();

    float sj = 0.f, qj = 0.f;
    for (int it = 0; it < 16; ++it) {
        size_t rowbase = (size_t)blockIdx.x*512 + it*32;
        __syncthreads();
        for (int i = t; i < 2048; i += 256) {
            int r = i >> 6, c = i & 63;
            float v = d_rr[(rowbase + r)*64 + c];
            v = fmaxf((v - bn1[c])*bn1[64+c]*bn1[128+c] + bn1[192+c], 0.f);
            rS[r][c] = v;
        }
        __syncthreads();
        float acc = bw1s[j];
        #pragma unroll 8
        for (int c = 0; c < 64; ++c) acc += rS[rw][c] * ww1s[c][j];
        d_w1[(rowbase + rw)*8 + j] = acc;
        sj += acc; qj += acc*acc;
    }
    __shared__ float red2[32][8][2];
    red2[rw][j][0] = sj; red2[rw][j][1] = qj;
    __syncthreads();
    for (int st = 16; st; st >>= 1) {
        if (rw < st) {
            red2[rw][j][0] += red2[rw+st][j][0];
            red2[rw][j][1] += red2[rw+st][j][1];
        }
        __syncthreads();
    }
    if (rw == 0) {
        d_part[(size_t)blockIdx.x*16 + j]     = red2[0][j][0];
        d_part[(size_t)blockIdx.x*16 + 8 + j] = red2[0][j][1];
    }
}

// ---------------- L9: w2, softmax over K, weighted combine ----------------
__global__ __launch_bounds__(256) void final_kernel(
    const float* __restrict__ g2, const float* __restrict__ bt2,
    const float* __restrict__ ww2, const float* __restrict__ bw2,
    float* __restrict__ out)
{
    int t = threadIdx.x, w = t >> 5, l = t & 31;
    int n = blockIdx.x*8 + w;
    __shared__ float ww2s[64];
    __shared__ float prm[32];
    __shared__ float bw2s[8];
    __shared__ float wsh[8][16][8];
    __shared__ float inv[8][8];
    if (t < 64) ww2s[t] = ww2[t];
    if (t < 8) {
        prm[t]      = d_stats[136 + t];
        prm[8 + t]  = d_stats[144 + t];
        prm[16 + t] = g2[t];
        prm[24 + t] = bt2[t];
        bw2s[t]     = bw2[t];
    }
    __syncthreads();

    #pragma unroll
    for (int rep = 0; rep < 4; ++rep) {
        int e = rep*32 + l;
        int tt = e >> 3, j = e & 7;
        const float* w1row = &d_w1[((size_t)n*16 + tt)*8];
        float acc = bw2s[j];
        #pragma unroll
        for (int c = 0; c < 8; ++c) {
            float v = fmaxf((w1row[c] - prm[c])*prm[8+c]*prm[16+c] + prm[24+c], 0.f);
            acc += v * ww2s[c*8 + j];
        }
        wsh[w][tt][j] = acc;
    }
    __syncwarp();
    if (l < 8) {
        float m = -3.4e38f;
        #pragma unroll
        for (int tt = 0; tt < 16; ++tt) m = fmaxf(m, wsh[w][tt][l]);
        float ssum = 0.f;
        #pragma unroll
        for (int tt = 0; tt < 16; ++tt) {
            float e_ = expf(wsh[w][tt][l] - m);
            wsh[w][tt][l] = e_;
            ssum += e_;
        }
        inv[w][l] = 1.f / ssum;
    }
    __syncwarp();
    int j = l & 7;
    float acc0 = 0.f, acc1 = 0.f;
    const int* idxr = &d_idxv[(size_t)n*16];
    #pragma unroll
    for (int tt = 0; tt < 16; ++tt) {
        int gi = idxr[tt];
        float wt = wsh[w][tt][j];
        size_t prb = ((size_t)n*16 + tt)*64;
        acc0 += (d_xv[(size_t)gi*64 + l]      + d_pr[prb + l])      * wt;
        acc1 += (d_xv[(size_t)gi*64 + 32 + l] + d_pr[prb + 32 + l]) * wt;
    }
    float iv = inv[w][j];
    out[(size_t)n*64 + l]      = acc0 * iv;
    out[(size_t)n*64 + 32 + l] = acc1 * iv;
}

// ---------------- launch ----------------
extern "C" void kernel_launch(void* const* d_in, const int* in_sizes, int n_in,
                              void* d_out, int out_size)
{
    const float* p   = (const float*)d_in[0];
    const float* x   = (const float*)d_in[1];
    // d_in[2] = o (batch sizes, structurally fixed -> unused)
    const float* wq  = (const float*)d_in[3];  const float* bq  = (const float*)d_in[4];
    const float* wk  = (const float*)d_in[5];  const float* bk  = (const float*)d_in[6];
    const float* wv  = (const float*)d_in[7];  const float* bv  = (const float*)d_in[8];
    const float* wp1 = (const float*)d_in[9];  const float* bp1 = (const float*)d_in[10];
    const float* gp  = (const float*)d_in[11]; const float* btp = (const float*)d_in[12];
    const float* wp2 = (const float*)d_in[13]; const float* bp2 = (const float*)d_in[14];
    const float* g1  = (const float*)d_in[15]; const float* bt1 = (const float*)d_in[16];
    const float* ww1 = (const float*)d_in[17]; const float* bw1 = (const float*)d_in[18];
    const float* g2  = (const float*)d_in[19]; const float* bt2 = (const float*)d_in[20];
    const float* ww2 = (const float*)d_in[21]; const float* bw2 = (const float*)d_in[22];
    float* out = (float*)d_out;

    qkv_kernel<<<2048, 256>>>(x, wq, bq, wk, bk, wv, bv);
    sq_kernel<<<4096, 256>>>();
    dim3 kg(64, 8, 2);
    knn_kernel<<<kg, 256>>>();
    hstats_kernel<<<512, 256>>>(p, wp1, bp1);
    finalize_kernel<<<1, 256>>>(3, 512, 0);
    pr_r_kernel<<<1024, 256>>>(gp, btp, wp2, bp2);
    finalize_kernel<<<1, 256>>>(64, 1024, 8);
    w1_kernel<<<1024, 256>>>(g1, bt1, ww1, bw1);
    finalize_kernel<<<1, 256>>>(8, 1024, 136);
    final_kernel<<<4096, 256>>>(g2, bt2, ww2, bw2, out);
}

// round 3
// speedup vs baseline: 1.7379x; 1.7379x over previous
#include <cuda_runtime.h>
#include <math.h>

// Problem constants
#define BATCH   8
#define NPB     4096
#define NPTS    (BATCH*NPB)      // 32768
#define KNN     16
#define CF      64
#define NKROWS  (NPTS*KNN)       // 524288
#define HDIM    8

// ---------------- scratch (device globals; no allocation) ----------------
__device__ float d_xq[NPTS*CF];
__device__ float d_xk[NPTS*CF];
__device__ float d_xv[NPTS*CF];
__device__ float d_sqk[NPTS];
__device__ float d_sqv[NPTS];
__device__ int   d_idxk[NKROWS];
__device__ int   d_idxv[NKROWS];
__device__ float d_h[NKROWS*3];
__device__ float d_pr[(size_t)NKROWS*CF];   // 128 MB
__device__ float d_rr[(size_t)NKROWS*CF];   // 128 MB
__device__ float d_w1[NKROWS*HDIM];
__device__ float d_part[1024*128];
// stats: [0..2] mean_h, [3..5] rstd_h, [8..71] mean_r, [72..135] rstd_r,
//        [136..143] mean_w, [144..151] rstd_w
__device__ float d_stats[160];

// ---------------- no-op (profiling launch-index alignment) ----------------
__global__ void noop_kernel() {}

// ---------------- L1: q/k/v projections ----------------
__global__ __launch_bounds__(256) void qkv_kernel(
    const float* __restrict__ x,
    const float* __restrict__ wq, const float* __restrict__ bq,
    const float* __restrict__ wk, const float* __restrict__ bk,
    const float* __restrict__ wv, const float* __restrict__ bv)
{
    __shared__ float xs[16][64];
    __shared__ float ws[64][64];
    int t = threadIdx.x;
    int row = t >> 4, quad = t & 15;
    int rbase = blockIdx.x * 16;
    for (int i = t; i < 16*64; i += 256)
        xs[i>>6][i&63] = x[(size_t)(rbase + (i>>6))*64 + (i&63)];

    for (int m = 0; m < 3; ++m) {
        const float* W = (m==0) ? wq : (m==1) ? wk : wv;
        const float* Bv = (m==0) ? bq : (m==1) ? bk : bv;
        float* O = (m==0) ? d_xq : (m==1) ? d_xk : d_xv;
        __syncthreads();
        for (int i = t; i < 64*64; i += 256) ws[i>>6][i&63] = W[i];
        __syncthreads();
        float a0 = Bv[quad*4+0], a1 = Bv[quad*4+1], a2 = Bv[quad*4+2], a3 = Bv[quad*4+3];
        #pragma unroll 8
        for (int i = 0; i < 64; ++i) {
            float xv_ = xs[row][i];
            float4 w4 = *(const float4*)&ws[i][quad*4];
            a0 += xv_*w4.x; a1 += xv_*w4.y; a2 += xv_*w4.z; a3 += xv_*w4.w;
        }
        float4 o4; o4.x=a0; o4.y=a1; o4.z=a2; o4.w=a3;
        *(float4*)&O[(size_t)(rbase+row)*64 + quad*4] = o4;
    }
}

// ---------------- L1b: squared norms of xk and xv ----------------
__global__ __launch_bounds__(256) void sq_kernel()
{
    int w = threadIdx.x >> 5, l = threadIdx.x & 31;
    int row = blockIdx.x*8 + w;
    float a = d_xk[(size_t)row*64 + l], b = d_xk[(size_t)row*64 + 32 + l];
    float s = a*a + b*b;
    #pragma unroll
    for (int o = 16; o; o >>= 1) s += __shfl_xor_sync(0xffffffffu, s, o);
    if (l == 0) d_sqk[row] = s;
    a = d_xv[(size_t)row*64 + l]; b = d_xv[(size_t)row*64 + 32 + l];
    s = a*a + b*b;
    #pragma unroll
    for (int o = 16; o; o >>= 1) s += __shfl_xor_sync(0xffffffffu, s, o);
    if (l == 0) d_sqv[row] = s;
}

// ---------------- L2: fused distance + top-16 KNN (v2: 8x8 reg tile) -------
// grid (32, 8, 2): x = 128-query tile, y = batch, z = space (0:k, 1:v)
// dynamic smem (floats): sQ[64][128] sw, sC[64][128] sw, sD[128][64] sw,
//                        sqQ[128], sqC[128]  -> 24832 floats = 99328 B
#define KNN_SMEM_BYTES (24832*4)

// strict-less insert (valid while candidate idx strictly increases)
#define INS_STRICT(dd, ci) do {                                       \
    float _d = (dd);                                                  \
    if (_d < listD[15]) {                                             \
        float cd = _d; int cix = (ci);                                \
        _Pragma("unroll")                                             \
        for (int e = 0; e < 16; ++e) {                                \
            bool bt = cd < listD[e];                                  \
            float od = listD[e]; int oi = listI[e];                   \
            if (bt) { listD[e] = cd; listI[e] = cix; cd = od; cix = oi; } \
        }                                                             \
    }                                                                 \
} while (0)

__global__ __launch_bounds__(256) void knn_kernel()
{
    extern __shared__ float sm[];
    float* sQ  = sm;            // [feat 64][pt 128] granule-swizzled
    float* sC  = sm + 8192;
    float* sD  = sm + 16384;    // [q 128][cand 64] granule-swizzled
    float* sqQ = sm + 24576;
    float* sqC = sm + 24704;

    const int sp = blockIdx.z;
    const float* feat = sp ? d_xv  : d_xk;
    const float* sqA  = sp ? d_sqv : d_sqk;
    int*         outIx = sp ? d_idxv : d_idxk;
    const int batch = blockIdx.y;
    const int qbase = batch*NPB + blockIdx.x*128;

    const int t  = threadIdx.x;
    const int tq = t >> 4, tc = t & 15;     // 16x16 thread grid, 8x8 frags
    const int qown = t >> 1, h = t & 1;     // scan roles

    // ---- load Q tile transposed+swizzled: sQ[f*128 + ((pt>>2)^(f&15))*4 + (pt&3)]
    for (int i = t; i < 2048; i += 256) {
        int r = i >> 4, f4 = i & 15;
        float4 g = *(const float4*)&feat[(size_t)(qbase + r)*64 + f4*4];
        int gr = r >> 2, ro = r & 3;
        int f = 4*f4;
        sQ[(f+0)*128 + ((gr ^ ((f+0)&15))<<2) + ro] = g.x;
        sQ[(f+1)*128 + ((gr ^ ((f+1)&15))<<2) + ro] = g.y;
        sQ[(f+2)*128 + ((gr ^ ((f+2)&15))<<2) + ro] = g.z;
        sQ[(f+3)*128 + ((gr ^ ((f+3)&15))<<2) + ro] = g.w;
    }
    if (t < 128) sqQ[t] = sqA[qbase + t];

    float listD[16]; int listI[16];
    #pragma unroll
    for (int e = 0; e < 16; ++e) { listD[e] = 3.4e38f; listI[e] = 0x7fffffff; }

    for (int tile = 0; tile < 32; ++tile) {
        const int cbase = batch*NPB + tile*128;
        // ---- load C tile transposed+swizzled (prev FMA done via stage syncs)
        for (int i = t; i < 2048; i += 256) {
            int r = i >> 4, f4 = i & 15;
            float4 g = *(const float4*)&feat[(size_t)(cbase + r)*64 + f4*4];
            int gr = r >> 2, ro = r & 3;
            int f = 4*f4;
            sC[(f+0)*128 + ((gr ^ ((f+0)&15))<<2) + ro] = g.x;
            sC[(f+1)*128 + ((gr ^ ((f+1)&15))<<2) + ro] = g.y;
            sC[(f+2)*128 + ((gr ^ ((f+2)&15))<<2) + ro] = g.z;
            sC[(f+3)*128 + ((gr ^ ((f+3)&15))<<2) + ro] = g.w;
        }
        if (t < 128) sqC[t] = sqA[cbase + t];
        __syncthreads();

        // ---- 8x8 GEMM fragment: queries tq*8..+7, cands {tc*4..+3, 64+tc*4..+3}
        float acc[64];
        #pragma unroll
        for (int e = 0; e < 64; ++e) acc[e] = 0.f;

        #pragma unroll 8
        for (int kk = 0; kk < 64; ++kk) {
            int ks = kk & 15;
            const float* rowQ = sQ + kk*128;
            const float* rowC = sC + kk*128;
            float4 q0 = *(const float4*)(rowQ + (((2*tq)   ^ ks) << 2));
            float4 q1 = *(const float4*)(rowQ + (((2*tq+1) ^ ks) << 2));
            float4 c0 = *(const float4*)(rowC + ((tc ^ ks) << 2));
            float4 c1 = *(const float4*)(rowC + (((tc ^ ks) + 16) << 2));
            float qv[8] = {q0.x,q0.y,q0.z,q0.w,q1.x,q1.y,q1.z,q1.w};
            float cv[8] = {c0.x,c0.y,c0.z,c0.w,c1.x,c1.y,c1.z,c1.w};
            #pragma unroll
            for (int a2 = 0; a2 < 8; ++a2)
                #pragma unroll
                for (int b2 = 0; b2 < 8; ++b2)
                    acc[a2*8+b2] += qv[a2]*cv[b2];
        }

        // ---- two 64-cand stages: materialize dist, scan top-16
        #pragma unroll
        for (int s = 0; s < 2; ++s) {
            __syncthreads();     // prev sD consumers done
            float sc0 = sqC[s*64 + tc*4+0];
            float sc1 = sqC[s*64 + tc*4+1];
            float sc2 = sqC[s*64 + tc*4+2];
            float sc3 = sqC[s*64 + tc*4+3];
            #pragma unroll
            for (int i = 0; i < 8; ++i) {
                int row = tq*8 + i;
                float sqq = sqQ[row];
                float4 v;
                v.x = sqq + sc0 - 2.f*acc[i*8 + s*4 + 0];
                v.y = sqq + sc1 - 2.f*acc[i*8 + s*4 + 1];
                v.z = sqq + sc2 - 2.f*acc[i*8 + s*4 + 2];
                v.w = sqq + sc3 - 2.f*acc[i*8 + s*4 + 3];
                *(float4*)&sD[row*64 + ((tc ^ (row & 15))<<2)] = v;
            }
            __syncthreads();
            #pragma unroll
            for (int g = 0; g < 8; ++g) {
                int lg = h*8 + g;
                float4 dv = *(const float4*)&sD[qown*64 + ((lg ^ (qown & 15))<<2)];
                int cb = cbase + s*64 + lg*4;
                float mn = fminf(fminf(dv.x, dv.y), fminf(dv.z, dv.w));
                if (mn < listD[15]) {
                    INS_STRICT(dv.x, cb+0);
                    INS_STRICT(dv.y, cb+1);
                    INS_STRICT(dv.z, cb+2);
                    INS_STRICT(dv.w, cb+3);
                }
            }
        }
    }

    // ---- merge the two 16-lists per query (disjoint candidate sets)
    __syncthreads();
    int* iC = (int*)sC;
    #pragma unroll
    for (int e = 0; e < 16; ++e) {
        sD[qown*33 + h*16 + e] = listD[e];
        iC[qown*33 + h*16 + e] = listI[e];
    }
    __syncthreads();
    if (h == 0) {
        #pragma unroll
        for (int e = 0; e < 16; ++e) {
            float dd = sD[qown*33 + 16 + e];
            int   ci = iC[qown*33 + 16 + e];
            if (dd < listD[15] || (dd == listD[15] && ci < listI[15])) {
                float cd = dd; int cix = ci;
                #pragma unroll
                for (int e2 = 0; e2 < 16; ++e2) {
                    bool bt = (cd < listD[e2]) || (cd == listD[e2] && cix < listI[e2]);
                    float od = listD[e2]; int oi = listI[e2];
                    if (bt) { listD[e2] = cd; listI[e2] = cix; cd = od; cix = oi; }
                }
            }
        }
        int gq = qbase + qown;
        #pragma unroll
        for (int e = 0; e < 16; ++e) outIx[(size_t)gq*16 + e] = listI[e];
    }
}

// ---------------- L3: h = p_rel @ wp1 + bp1, plus partial stats (3 ch) ----------------
__global__ __launch_bounds__(256) void hstats_kernel(
    const float* __restrict__ p, const float* __restrict__ wp1, const float* __restrict__ bp1)
{
    int t = threadIdx.x;
    float w[9];
    #pragma unroll
    for (int j = 0; j < 9; ++j) w[j] = wp1[j];
    float b0 = bp1[0], b1 = bp1[1], b2 = bp1[2];
    float s0=0,s1=0,s2=0,q0=0,q1=0,q2=0;
    for (int rep = 0; rep < 4; ++rep) {
        int row = blockIdx.x*1024 + rep*256 + t;
        int n = row >> 4;
        int gi = d_idxk[row];
        float r0 = p[(size_t)gi*3+0] - p[(size_t)n*3+0];
        float r1 = p[(size_t)gi*3+1] - p[(size_t)n*3+1];
        float r2 = p[(size_t)gi*3+2] - p[(size_t)n*3+2];
        float h0 = r0*w[0] + r1*w[3] + r2*w[6] + b0;
        float h1 = r0*w[1] + r1*w[4] + r2*w[7] + b1;
        float h2 = r0*w[2] + r1*w[5] + r2*w[8] + b2;
        d_h[(size_t)row*3+0] = h0; d_h[(size_t)row*3+1] = h1; d_h[(size_t)row*3+2] = h2;
        s0 += h0; s1 += h1; s2 += h2;
        q0 += h0*h0; q1 += h1*h1; q2 += h2*h2;
    }
    __shared__ float red[6][256];
    red[0][t]=s0; red[1][t]=s1; red[2][t]=s2; red[3][t]=q0; red[4][t]=q1; red[5][t]=q2;
    __syncthreads();
    for (int st = 128; st; st >>= 1) {
        if (t < st) {
            #pragma unroll
            for (int e = 0; e < 6; ++e) red[e][t] += red[e][t+st];
        }
        __syncthreads();
    }
    if (t < 6) d_part[blockIdx.x*6 + t] = red[t][0];
}

// ---------------- generic deterministic finalize (mean / rstd) ----------------
__global__ __launch_bounds__(256) void finalize_kernel(int nch, int nblocks, int statOff)
{
    __shared__ double sh[512];
    int t = threadIdx.x;
    int nsl = 256 / nch;
    int c = t % nch, sl = t / nch;
    double s = 0.0, q = 0.0;
    if (sl < nsl) {
        for (int b = sl; b < nblocks; b += nsl) {
            s += (double)d_part[(size_t)b*2*nch + c];
            q += (double)d_part[(size_t)b*2*nch + nch + c];
        }
    }
    sh[t] = s; sh[256 + t] = q;
    __syncthreads();
    if (t < nch) {
        double S = 0.0, Q = 0.0;
        for (int s2 = 0; s2 < nsl; ++s2) { S += sh[s2*nch + t]; Q += sh[256 + s2*nch + t]; }
        double cnt = (double)NKROWS;
        double m = S / cnt;
        double v = Q / cnt - m*m;
        d_stats[statOff + t]        = (float)m;
        d_stats[statOff + nch + t]  = (float)(1.0 / sqrt(v + 1e-5));
    }
}

// ---------------- L5: p_r and r, plus partial stats over r (64 ch) ----------------
__global__ __launch_bounds__(256) void pr_r_kernel(
    const float* __restrict__ gp, const float* __restrict__ btp,
    const float* __restrict__ wp2, const float* __restrict__ bp2)
{
    int t = threadIdx.x;
    int rl = t >> 4, quad = t & 15;
    __shared__ float wp2s[3][64];
    __shared__ float bp2s[64];
    __shared__ float bnp[12];
    if (t < 192) wp2s[t/64][t%64] = wp2[t];
    if (t < 64)  bp2s[t] = bp2[t];
    if (t < 6)   bnp[t] = d_stats[t];
    if (t >= 6 && t < 9)   bnp[t] = gp[t-6];
    if (t >= 9 && t < 12)  bnp[t] = btp[t-9];
    __syncthreads();

    float4 w0 = *(const float4*)&wp2s[0][quad*4];
    float4 w1 = *(const float4*)&wp2s[1][quad*4];
    float4 w2 = *(const float4*)&wp2s[2][quad*4];
    float4 bp4 = *(const float4*)&bp2s[quad*4];
    float sx=0,sy=0,sz=0,sw=0, qx=0,qy=0,qz=0,qw=0;

    for (int it = 0; it < 32; ++it) {
        size_t row = (size_t)blockIdx.x*512 + it*16 + rl;
        float h0 = d_h[row*3+0], h1 = d_h[row*3+1], h2 = d_h[row*3+2];
        h0 = fmaxf((h0 - bnp[0])*bnp[3]*bnp[6] + bnp[9],  0.f);
        h1 = fmaxf((h1 - bnp[1])*bnp[4]*bnp[7] + bnp[10], 0.f);
        h2 = fmaxf((h2 - bnp[2])*bnp[5]*bnp[8] + bnp[11], 0.f);
        float4 pr;
        pr.x = bp4.x + h0*w0.x + h1*w1.x + h2*w2.x;
        pr.y = bp4.y + h0*w0.y + h1*w1.y + h2*w2.y;
        pr.z = bp4.z + h0*w0.z + h1*w1.z + h2*w2.z;
        pr.w = bp4.w + h0*w0.w + h1*w1.w + h2*w2.w;
        int n  = (int)(row >> 4);
        int gi = d_idxk[row];
        float4 xk4 = *(const float4*)&d_xk[(size_t)gi*64 + quad*4];
        float4 xq4 = *(const float4*)&d_xq[(size_t)n*64 + quad*4];
        float4 r4;
        r4.x = xk4.x - xq4.x + pr.x;
        r4.y = xk4.y - xq4.y + pr.y;
        r4.z = xk4.z - xq4.z + pr.z;
        r4.w = xk4.w - xq4.w + pr.w;
        *(float4*)&d_pr[row*64 + quad*4] = pr;
        *(float4*)&d_rr[row*64 + quad*4] = r4;
        sx += r4.x; sy += r4.y; sz += r4.z; sw += r4.w;
        qx += r4.x*r4.x; qy += r4.y*r4.y; qz += r4.z*r4.z; qw += r4.w*r4.w;
    }
    __shared__ float red[16][16][8];
    red[rl][quad][0]=sx; red[rl][quad][1]=sy; red[rl][quad][2]=sz; red[rl][quad][3]=sw;
    red[rl][quad][4]=qx; red[rl][quad][5]=qy; red[rl][quad][6]=qz; red[rl][quad][7]=qw;
    __syncthreads();
    for (int st = 8; st; st >>= 1) {
        if (rl < st) {
            #pragma unroll
            for (int e = 0; e < 8; ++e) red[rl][quad][e] += red[rl+st][quad][e];
        }
        __syncthreads();
    }
    if (rl == 0) {
        #pragma unroll
        for (int j = 0; j < 4; ++j) {
            d_part[(size_t)blockIdx.x*128 + quad*4 + j]      = red[0][quad][j];
            d_part[(size_t)blockIdx.x*128 + 64 + quad*4 + j] = red[0][quad][4+j];
        }
    }
}

// ---------------- L7: w1 = relu(bn1(r)) @ ww1 + bw1, plus partial stats (8 ch) ----------------
__global__ __launch_bounds__(256) void w1_kernel(
    const float* __restrict__ g1, const float* __restrict__ bt1,
    const float* __restrict__ ww1, const float* __restrict__ bw1)
{
    int t = threadIdx.x;
    int rw = t >> 3, j = t & 7;
    __shared__ float rS[32][65];
    __shared__ float ww1s[64][8];
    __shared__ float bn1[256];
    __shared__ float bw1s[8];
    if (t < 64) {
        bn1[t]       = d_stats[8 + t];
        bn1[64 + t]  = d_stats[72 + t];
        bn1[128 + t] = g1[t];
        bn1[192 + t] = bt1[t];
    }
    if (t < 8) bw1s[t] = bw1[t];
    for (int i = t; i < 512; i += 256) ww1s[i>>3][i&7] = ww1[i];
    __syncthreads();

    float sj = 0.f, qj = 0.f;
    for (int it = 0; it < 16; ++it) {
        size_t rowbase = (size_t)blockIdx.x*512 + it*32;
        __syncthreads();
        for (int i = t; i < 2048; i += 256) {
            int r = i >> 6, c = i & 63;
            float v = d_rr[(rowbase + r)*64 + c];
            v = fmaxf((v - bn1[c])*bn1[64+c]*bn1[128+c] + bn1[192+c], 0.f);
            rS[r][c] = v;
        }
        __syncthreads();
        float acc = bw1s[j];
        #pragma unroll 8
        for (int c = 0; c < 64; ++c) acc += rS[rw][c] * ww1s[c][j];
        d_w1[(rowbase + rw)*8 + j] = acc;
        sj += acc; qj += acc*acc;
    }
    __shared__ float red2[32][8][2];
    red2[rw][j][0] = sj; red2[rw][j][1] = qj;
    __syncthreads();
    for (int st = 16; st; st >>= 1) {
        if (rw < st) {
            red2[rw][j][0] += red2[rw+st][j][0];
            red2[rw][j][1] += red2[rw+st][j][1];
        }
        __syncthreads();
    }
    if (rw == 0) {
        d_part[(size_t)blockIdx.x*16 + j]     = red2[0][j][0];
        d_part[(size_t)blockIdx.x*16 + 8 + j] = red2[0][j][1];
    }
}

// ---------------- L9: w2, softmax over K, weighted combine ----------------
__global__ __launch_bounds__(256) void final_kernel(
    const float* __restrict__ g2, const float* __restrict__ bt2,
    const float* __restrict__ ww2, const float* __restrict__ bw2,
    float* __restrict__ out)
{
    int t = threadIdx.x, w = t >> 5, l = t & 31;
    int n = blockIdx.x*8 + w;
    __shared__ float ww2s[64];
    __shared__ float prm[32];
    __shared__ float bw2s[8];
    __shared__ float wsh[8][16][8];
    __shared__ float inv[8][8];
    if (t < 64) ww2s[t] = ww2[t];
    if (t < 8) {
        prm[t]      = d_stats[136 + t];
        prm[8 + t]  = d_stats[144 + t];
        prm[16 + t] = g2[t];
        prm[24 + t] = bt2[t];
        bw2s[t]     = bw2[t];
    }
    __syncthreads();

    #pragma unroll
    for (int rep = 0; rep < 4; ++rep) {
        int e = rep*32 + l;
        int tt = e >> 3, j = e & 7;
        const float* w1row = &d_w1[((size_t)n*16 + tt)*8];
        float acc = bw2s[j];
        #pragma unroll
        for (int c = 0; c < 8; ++c) {
            float v = fmaxf((w1row[c] - prm[c])*prm[8+c]*prm[16+c] + prm[24+c], 0.f);
            acc += v * ww2s[c*8 + j];
        }
        wsh[w][tt][j] = acc;
    }
    __syncwarp();
    if (l < 8) {
        float m = -3.4e38f;
        #pragma unroll
        for (int tt = 0; tt < 16; ++tt) m = fmaxf(m, wsh[w][tt][l]);
        float ssum = 0.f;
        #pragma unroll
        for (int tt = 0; tt < 16; ++tt) {
            float e_ = expf(wsh[w][tt][l] - m);
            wsh[w][tt][l] = e_;
            ssum += e_;
        }
        inv[w][l] = 1.f / ssum;
    }
    __syncwarp();
    int j = l & 7;
    float acc0 = 0.f, acc1 = 0.f;
    const int* idxr = &d_idxv[(size_t)n*16];
    #pragma unroll
    for (int tt = 0; tt < 16; ++tt) {
        int gi = idxr[tt];
        float wt = wsh[w][tt][j];
        size_t prb = ((size_t)n*16 + tt)*64;
        acc0 += (d_xv[(size_t)gi*64 + l]      + d_pr[prb + l])      * wt;
        acc1 += (d_xv[(size_t)gi*64 + 32 + l] + d_pr[prb + 32 + l]) * wt;
    }
    float iv = inv[w][j];
    out[(size_t)n*64 + l]      = acc0 * iv;
    out[(size_t)n*64 + 32 + l] = acc1 * iv;
}

// ---------------- launch ----------------
extern "C" void kernel_launch(void* const* d_in, const int* in_sizes, int n_in,
                              void* d_out, int out_size)
{
    const float* p   = (const float*)d_in[0];
    const float* x   = (const float*)d_in[1];
    // d_in[2] = o (batch sizes, structurally fixed -> unused)
    const float* wq  = (const float*)d_in[3];  const float* bq  = (const float*)d_in[4];
    const float* wk  = (const float*)d_in[5];  const float* bk  = (const float*)d_in[6];
    const float* wv  = (const float*)d_in[7];  const float* bv  = (const float*)d_in[8];
    const float* wp1 = (const float*)d_in[9];  const float* bp1 = (const float*)d_in[10];
    const float* gp  = (const float*)d_in[11]; const float* btp = (const float*)d_in[12];
    const float* wp2 = (const float*)d_in[13]; const float* bp2 = (const float*)d_in[14];
    const float* g1  = (const float*)d_in[15]; const float* bt1 = (const float*)d_in[16];
    const float* ww1 = (const float*)d_in[17]; const float* bw1 = (const float*)d_in[18];
    const float* g2  = (const float*)d_in[19]; const float* bt2 = (const float*)d_in[20];
    const float* ww2 = (const float*)d_in[21]; const float* bw2 = (const float*)d_in[22];
    float* out = (float*)d_out;

    cudaFuncSetAttribute(knn_kernel, cudaFuncAttributeMaxDynamicSharedMemorySize,
                         KNN_SMEM_BYTES);

    qkv_kernel<<<2048, 256>>>(x, wq, bq, wk, bk, wv, bv);   // launch 1
    sq_kernel<<<4096, 256>>>();                             // launch 2
    noop_kernel<<<1, 32>>>();                               // launch 3 (ncu alignment)
    dim3 kg(32, 8, 2);
    knn_kernel<<<kg, 256, KNN_SMEM_BYTES>>>();              // launch 4 <- profiled
    hstats_kernel<<<512, 256>>>(p, wp1, bp1);
    finalize_kernel<<<1, 256>>>(3, 512, 0);
    pr_r_kernel<<<1024, 256>>>(gp, btp, wp2, bp2);
    finalize_kernel<<<1, 256>>>(64, 1024, 8);
    w1_kernel<<<1024, 256>>>(g1, bt1, ww1, bw1);
    finalize_kernel<<<1, 256>>>(8, 1024, 136);
    final_kernel<<<4096, 256>>>(g2, bt2, ww2, bw2, out);
}

// round 4
// speedup vs baseline: 1.9027x; 1.0948x over previous
#include <cuda_runtime.h>
#include <math.h>

// Problem constants
#define BATCH   8
#define NPB     4096
#define NPTS    (BATCH*NPB)      // 32768
#define KNN     16
#define CF      64
#define NKROWS  (NPTS*KNN)       // 524288
#define HDIM    8

// ---------------- scratch (device globals; no allocation) ----------------
__device__ float d_xq[NPTS*CF];
__device__ float d_xk[NPTS*CF];
__device__ float d_xv[NPTS*CF];
__device__ float d_sqk[NPTS];
__device__ float d_sqv[NPTS];
__device__ int   d_idxk[NKROWS];
__device__ int   d_idxv[NKROWS];
__device__ float d_h[NKROWS*3];
__device__ float d_rr[(size_t)NKROWS*CF];   // 128 MB
__device__ float d_w1[NKROWS*HDIM];
__device__ float d_part[1024*128];
// stats: [0..2] mean_h, [3..5] rstd_h, [8..71] mean_r, [72..135] rstd_r,
//        [136..143] mean_w, [144..151] rstd_w
__device__ float d_stats[160];

// ---------------- f32x2 helpers (sm_100+) ----------------
__device__ __forceinline__ unsigned long long dup2(float x) {
    unsigned long long r;
    asm("mov.b64 %0, {%1, %1};" : "=l"(r) : "f"(x));
    return r;
}
__device__ __forceinline__ void ffma2(unsigned long long& a,
                                      unsigned long long b,
                                      unsigned long long c) {
    asm("fma.rn.f32x2 %0, %1, %2, %0;" : "+l"(a) : "l"(b), "l"(c));
}
__device__ __forceinline__ void unpk(unsigned long long v, float& lo, float& hi) {
    asm("mov.b64 {%0, %1}, %2;" : "=f"(lo), "=f"(hi) : "l"(v));
}

// ---------------- no-op (profiling launch-index alignment) ----------------
__global__ void noop_kernel() {}

// ---------------- L1: q/k/v projections ----------------
__global__ __launch_bounds__(256) void qkv_kernel(
    const float* __restrict__ x,
    const float* __restrict__ wq, const float* __restrict__ bq,
    const float* __restrict__ wk, const float* __restrict__ bk,
    const float* __restrict__ wv, const float* __restrict__ bv)
{
    __shared__ float xs[16][64];
    __shared__ float ws[64][64];
    int t = threadIdx.x;
    int row = t >> 4, quad = t & 15;
    int rbase = blockIdx.x * 16;
    for (int i = t; i < 16*64; i += 256)
        xs[i>>6][i&63] = x[(size_t)(rbase + (i>>6))*64 + (i&63)];

    for (int m = 0; m < 3; ++m) {
        const float* W = (m==0) ? wq : (m==1) ? wk : wv;
        const float* Bv = (m==0) ? bq : (m==1) ? bk : bv;
        float* O = (m==0) ? d_xq : (m==1) ? d_xk : d_xv;
        __syncthreads();
        for (int i = t; i < 64*64; i += 256) ws[i>>6][i&63] = W[i];
        __syncthreads();
        float a0 = Bv[quad*4+0], a1 = Bv[quad*4+1], a2 = Bv[quad*4+2], a3 = Bv[quad*4+3];
        #pragma unroll 8
        for (int i = 0; i < 64; ++i) {
            float xv_ = xs[row][i];
            float4 w4 = *(const float4*)&ws[i][quad*4];
            a0 += xv_*w4.x; a1 += xv_*w4.y; a2 += xv_*w4.z; a3 += xv_*w4.w;
        }
        float4 o4; o4.x=a0; o4.y=a1; o4.z=a2; o4.w=a3;
        *(float4*)&O[(size_t)(rbase+row)*64 + quad*4] = o4;
    }
}

// ---------------- L1b: squared norms of xk and xv ----------------
__global__ __launch_bounds__(256) void sq_kernel()
{
    int w = threadIdx.x >> 5, l = threadIdx.x & 31;
    int row = blockIdx.x*8 + w;
    float a = d_xk[(size_t)row*64 + l], b = d_xk[(size_t)row*64 + 32 + l];
    float s = a*a + b*b;
    #pragma unroll
    for (int o = 16; o; o >>= 1) s += __shfl_xor_sync(0xffffffffu, s, o);
    if (l == 0) d_sqk[row] = s;
    a = d_xv[(size_t)row*64 + l]; b = d_xv[(size_t)row*64 + 32 + l];
    s = a*a + b*b;
    #pragma unroll
    for (int o = 16; o; o >>= 1) s += __shfl_xor_sync(0xffffffffu, s, o);
    if (l == 0) d_sqv[row] = s;
}

// ---------------- L2: fused distance + top-16 KNN (v3: f32x2, 2 CTAs/SM) --
// grid (32, 8, 2): x = 128-query tile, y = batch, z = space (0:k, 1:v)
// smem floats: sQ[64][128] sw (8192), sC[64][64] sw (4096),
//              sD[128][64] sw (8192), sqQ[128], sqC[64] -> 20672 fl = 82688 B
#define KNN_SMEM_BYTES (20672*4)

// strict-less insert (valid while candidate idx strictly increases)
#define INS_STRICT(dd, ci) do {                                       \
    float _d = (dd);                                                  \
    if (_d < listD[15]) {                                             \
        float cd = _d; int cix = (ci);                                \
        _Pragma("unroll")                                             \
        for (int e = 0; e < 16; ++e) {                                \
            bool bt = cd < listD[e];                                  \
            float od = listD[e]; int oi = listI[e];                   \
            if (bt) { listD[e] = cd; listI[e] = cix; cd = od; cix = oi; } \
        }                                                             \
    }                                                                 \
} while (0)

__global__ __launch_bounds__(256, 2) void knn_kernel()
{
    extern __shared__ float sm[];
    float* sQ  = sm;            // [feat 64][pt 128] granule-swizzled
    float* sC  = sm + 8192;     // [feat 64][cand 64] granule-swizzled
    float* sD  = sm + 12288;    // [q 128][cand 64] granule-swizzled
    float* sqQ = sm + 20480;
    float* sqC = sm + 20608;

    const int sp = blockIdx.z;
    const float* feat = sp ? d_xv  : d_xk;
    const float* sqA  = sp ? d_sqv : d_sqk;
    int*         outIx = sp ? d_idxv : d_idxk;
    const int batch = blockIdx.y;
    const int qbase = batch*NPB + blockIdx.x*128;

    const int t  = threadIdx.x;
    const int tq = t >> 4, tc = t & 15;     // 16x16 grid: 8 q-rows x 4 cands
    const int qown = t >> 1, h = t & 1;     // scan roles

    // ---- load Q tile transposed+swizzled: sQ[f*128 + ((pt>>2)^(f&15))*4 + (pt&3)]
    for (int i = t; i < 2048; i += 256) {
        int r = i >> 4, f4 = i & 15;
        float4 g = *(const float4*)&feat[(size_t)(qbase + r)*64 + f4*4];
        int gr = r >> 2, ro = r & 3;
        int f = 4*f4;
        sQ[(f+0)*128 + ((gr ^ ((f+0)&15))<<2) + ro] = g.x;
        sQ[(f+1)*128 + ((gr ^ ((f+1)&15))<<2) + ro] = g.y;
        sQ[(f+2)*128 + ((gr ^ ((f+2)&15))<<2) + ro] = g.z;
        sQ[(f+3)*128 + ((gr ^ ((f+3)&15))<<2) + ro] = g.w;
    }
    if (t < 128) sqQ[t] = sqA[qbase + t];

    float listD[16]; int listI[16];
    #pragma unroll
    for (int e = 0; e < 16; ++e) { listD[e] = 3.4e38f; listI[e] = 0x7fffffff; }

    for (int tile = 0; tile < 64; ++tile) {
        const int cbase = batch*NPB + tile*64;
        // prev-iter FMA done (sync C of prev iter) -> safe to overwrite sC
        for (int i = t; i < 1024; i += 256) {
            int r = i >> 4, f4 = i & 15;
            float4 g = *(const float4*)&feat[(size_t)(cbase + r)*64 + f4*4];
            int gr = r >> 2, ro = r & 3;
            int f = 4*f4;
            sC[(f+0)*64 + ((gr ^ ((f+0)&15))<<2) + ro] = g.x;
            sC[(f+1)*64 + ((gr ^ ((f+1)&15))<<2) + ro] = g.y;
            sC[(f+2)*64 + ((gr ^ ((f+2)&15))<<2) + ro] = g.z;
            sC[(f+3)*64 + ((gr ^ ((f+3)&15))<<2) + ro] = g.w;
        }
        if (t < 64) sqC[t] = sqA[cbase + t];
        __syncthreads();   // B: tile loaded; also: all threads past prev scan

        // ---- packed GEMM: 4 q-pairs x 4 cands per thread
        unsigned long long acc[4][4];
        #pragma unroll
        for (int a = 0; a < 4; ++a)
            #pragma unroll
            for (int b = 0; b < 4; ++b) acc[a][b] = 0ull;

        #pragma unroll 16
        for (int kk = 0; kk < 64; ++kk) {
            int ks = kk & 15;
            const float* rowQ = sQ + kk*128;
            const float* rowC = sC + kk*64;
            ulonglong2 qp0 = *(const ulonglong2*)(rowQ + (((2*tq)   ^ ks) << 2));
            ulonglong2 qp1 = *(const ulonglong2*)(rowQ + (((2*tq+1) ^ ks) << 2));
            float4 cv = *(const float4*)(rowC + ((tc ^ ks) << 2));
            unsigned long long b0 = dup2(cv.x), b1 = dup2(cv.y),
                               b2 = dup2(cv.z), b3 = dup2(cv.w);
            ffma2(acc[0][0], qp0.x, b0); ffma2(acc[0][1], qp0.x, b1);
            ffma2(acc[0][2], qp0.x, b2); ffma2(acc[0][3], qp0.x, b3);
            ffma2(acc[1][0], qp0.y, b0); ffma2(acc[1][1], qp0.y, b1);
            ffma2(acc[1][2], qp0.y, b2); ffma2(acc[1][3], qp0.y, b3);
            ffma2(acc[2][0], qp1.x, b0); ffma2(acc[2][1], qp1.x, b1);
            ffma2(acc[2][2], qp1.x, b2); ffma2(acc[2][3], qp1.x, b3);
            ffma2(acc[3][0], qp1.y, b0); ffma2(acc[3][1], qp1.y, b1);
            ffma2(acc[3][2], qp1.y, b2); ffma2(acc[3][3], qp1.y, b3);
        }

        // ---- distances into sD (prev scan done via sync B)
        float sc0 = sqC[tc*4+0], sc1 = sqC[tc*4+1],
              sc2 = sqC[tc*4+2], sc3 = sqC[tc*4+3];
        #pragma unroll
        for (int a = 0; a < 4; ++a) {
            int r0 = tq*8 + 2*a, r1 = r0 + 1;
            float d0l, d0h, d1l, d1h, d2l, d2h, d3l, d3h;
            unpk(acc[a][0], d0l, d0h);
            unpk(acc[a][1], d1l, d1h);
            unpk(acc[a][2], d2l, d2h);
            unpk(acc[a][3], d3l, d3h);
            float sqq0 = sqQ[r0], sqq1 = sqQ[r1];
            float4 v0, v1;
            v0.x = sqq0 + sc0 - 2.f*d0l;  v1.x = sqq1 + sc0 - 2.f*d0h;
            v0.y = sqq0 + sc1 - 2.f*d1l;  v1.y = sqq1 + sc1 - 2.f*d1h;
            v0.z = sqq0 + sc2 - 2.f*d2l;  v1.z = sqq1 + sc2 - 2.f*d2h;
            v0.w = sqq0 + sc3 - 2.f*d3l;  v1.w = sqq1 + sc3 - 2.f*d3h;
            *(float4*)&sD[r0*64 + ((tc ^ (r0 & 15))<<2)] = v0;
            *(float4*)&sD[r1*64 + ((tc ^ (r1 & 15))<<2)] = v1;
        }
        __syncthreads();   // C: sD complete

        // ---- scan: 2 threads/query, 32 cands each
        #pragma unroll
        for (int g = 0; g < 8; ++g) {
            int lg = h*8 + g;
            float4 dv = *(const float4*)&sD[qown*64 + ((lg ^ (qown & 15))<<2)];
            int cb = cbase + lg*4;
            float mn = fminf(fminf(dv.x, dv.y), fminf(dv.z, dv.w));
            if (mn < listD[15]) {
                INS_STRICT(dv.x, cb+0);
                INS_STRICT(dv.y, cb+1);
                INS_STRICT(dv.z, cb+2);
                INS_STRICT(dv.w, cb+3);
            }
        }
    }

    // ---- merge the two 16-lists per query (disjoint candidate sets)
    __syncthreads();
    int* iQ = (int*)sQ;
    #pragma unroll
    for (int e = 0; e < 16; ++e) {
        sD[qown*33 + h*16 + e] = listD[e];
        iQ[qown*33 + h*16 + e] = listI[e];
    }
    __syncthreads();
    if (h == 0) {
        #pragma unroll
        for (int e = 0; e < 16; ++e) {
            float dd = sD[qown*33 + 16 + e];
            int   ci = iQ[qown*33 + 16 + e];
            if (dd < listD[15] || (dd == listD[15] && ci < listI[15])) {
                float cd = dd; int cix = ci;
                #pragma unroll
                for (int e2 = 0; e2 < 16; ++e2) {
                    bool bt = (cd < listD[e2]) || (cd == listD[e2] && cix < listI[e2]);
                    float od = listD[e2]; int oi = listI[e2];
                    if (bt) { listD[e2] = cd; listI[e2] = cix; cd = od; cix = oi; }
                }
            }
        }
        int gq = qbase + qown;
        #pragma unroll
        for (int e = 0; e < 16; ++e) outIx[(size_t)gq*16 + e] = listI[e];
    }
}

// ---------------- L3: h = p_rel @ wp1 + bp1, plus partial stats (3 ch) ----------------
__global__ __launch_bounds__(256) void hstats_kernel(
    const float* __restrict__ p, const float* __restrict__ wp1, const float* __restrict__ bp1)
{
    int t = threadIdx.x;
    float w[9];
    #pragma unroll
    for (int j = 0; j < 9; ++j) w[j] = wp1[j];
    float b0 = bp1[0], b1 = bp1[1], b2 = bp1[2];
    float s0=0,s1=0,s2=0,q0=0,q1=0,q2=0;
    for (int rep = 0; rep < 4; ++rep) {
        int row = blockIdx.x*1024 + rep*256 + t;
        int n = row >> 4;
        int gi = d_idxk[row];
        float r0 = p[(size_t)gi*3+0] - p[(size_t)n*3+0];
        float r1 = p[(size_t)gi*3+1] - p[(size_t)n*3+1];
        float r2 = p[(size_t)gi*3+2] - p[(size_t)n*3+2];
        float h0 = r0*w[0] + r1*w[3] + r2*w[6] + b0;
        float h1 = r0*w[1] + r1*w[4] + r2*w[7] + b1;
        float h2 = r0*w[2] + r1*w[5] + r2*w[8] + b2;
        d_h[(size_t)row*3+0] = h0; d_h[(size_t)row*3+1] = h1; d_h[(size_t)row*3+2] = h2;
        s0 += h0; s1 += h1; s2 += h2;
        q0 += h0*h0; q1 += h1*h1; q2 += h2*h2;
    }
    __shared__ float red[6][256];
    red[0][t]=s0; red[1][t]=s1; red[2][t]=s2; red[3][t]=q0; red[4][t]=q1; red[5][t]=q2;
    __syncthreads();
    for (int st = 128; st; st >>= 1) {
        if (t < st) {
            #pragma unroll
            for (int e = 0; e < 6; ++e) red[e][t] += red[e][t+st];
        }
        __syncthreads();
    }
    if (t < 6) d_part[blockIdx.x*6 + t] = red[t][0];
}

// ---------------- generic deterministic finalize (mean / rstd) ----------------
__global__ __launch_bounds__(256) void finalize_kernel(int nch, int nblocks, int statOff)
{
    __shared__ double sh[512];
    int t = threadIdx.x;
    int nsl = 256 / nch;
    int c = t % nch, sl = t / nch;
    double s = 0.0, q = 0.0;
    if (sl < nsl) {
        for (int b = sl; b < nblocks; b += nsl) {
            s += (double)d_part[(size_t)b*2*nch + c];
            q += (double)d_part[(size_t)b*2*nch + nch + c];
        }
    }
    sh[t] = s; sh[256 + t] = q;
    __syncthreads();
    if (t < nch) {
        double S = 0.0, Q = 0.0;
        for (int s2 = 0; s2 < nsl; ++s2) { S += sh[s2*nch + t]; Q += sh[256 + s2*nch + t]; }
        double cnt = (double)NKROWS;
        double m = S / cnt;
        double v = Q / cnt - m*m;
        d_stats[statOff + t]        = (float)m;
        d_stats[statOff + nch + t]  = (float)(1.0 / sqrt(v + 1e-5));
    }
}

// ---------------- L5: r = xk_g - xq + p_r, plus partial stats over r (64 ch) -----
__global__ __launch_bounds__(256) void r_kernel(
    const float* __restrict__ gp, const float* __restrict__ btp,
    const float* __restrict__ wp2, const float* __restrict__ bp2)
{
    int t = threadIdx.x;
    int rl = t >> 4, quad = t & 15;
    __shared__ float wp2s[3][64];
    __shared__ float bp2s[64];
    __shared__ float bnp[12];
    if (t < 192) wp2s[t/64][t%64] = wp2[t];
    if (t < 64)  bp2s[t] = bp2[t];
    if (t < 6)   bnp[t] = d_stats[t];
    if (t >= 6 && t < 9)   bnp[t] = gp[t-6];
    if (t >= 9 && t < 12)  bnp[t] = btp[t-9];
    __syncthreads();

    float4 w0 = *(const float4*)&wp2s[0][quad*4];
    float4 w1 = *(const float4*)&wp2s[1][quad*4];
    float4 w2 = *(const float4*)&wp2s[2][quad*4];
    float4 bp4 = *(const float4*)&bp2s[quad*4];
    float sx=0,sy=0,sz=0,sw=0, qx=0,qy=0,qz=0,qw=0;

    for (int it = 0; it < 32; ++it) {
        size_t row = (size_t)blockIdx.x*512 + it*16 + rl;
        float h0 = d_h[row*3+0], h1 = d_h[row*3+1], h2 = d_h[row*3+2];
        h0 = fmaxf((h0 - bnp[0])*bnp[3]*bnp[6] + bnp[9],  0.f);
        h1 = fmaxf((h1 - bnp[1])*bnp[4]*bnp[7] + bnp[10], 0.f);
        h2 = fmaxf((h2 - bnp[2])*bnp[5]*bnp[8] + bnp[11], 0.f);
        float4 pr;
        pr.x = bp4.x + h0*w0.x + h1*w1.x + h2*w2.x;
        pr.y = bp4.y + h0*w0.y + h1*w1.y + h2*w2.y;
        pr.z = bp4.z + h0*w0.z + h1*w1.z + h2*w2.z;
        pr.w = bp4.w + h0*w0.w + h1*w1.w + h2*w2.w;
        int n  = (int)(row >> 4);
        int gi = d_idxk[row];
        float4 xk4 = *(const float4*)&d_xk[(size_t)gi*64 + quad*4];
        float4 xq4 = *(const float4*)&d_xq[(size_t)n*64 + quad*4];
        float4 r4;
        r4.x = xk4.x - xq4.x + pr.x;
        r4.y = xk4.y - xq4.y + pr.y;
        r4.z = xk4.z - xq4.z + pr.z;
        r4.w = xk4.w - xq4.w + pr.w;
        *(float4*)&d_rr[row*64 + quad*4] = r4;
        sx += r4.x; sy += r4.y; sz += r4.z; sw += r4.w;
        qx += r4.x*r4.x; qy += r4.y*r4.y; qz += r4.z*r4.z; qw += r4.w*r4.w;
    }
    __shared__ float red[16][16][8];
    red[rl][quad][0]=sx; red[rl][quad][1]=sy; red[rl][quad][2]=sz; red[rl][quad][3]=sw;
    red[rl][quad][4]=qx; red[rl][quad][5]=qy; red[rl][quad][6]=qz; red[rl][quad][7]=qw;
    __syncthreads();
    for (int st = 8; st; st >>= 1) {
        if (rl < st) {
            #pragma unroll
            for (int e = 0; e < 8; ++e) red[rl][quad][e] += red[rl+st][quad][e];
        }
        __syncthreads();
    }
    if (rl == 0) {
        #pragma unroll
        for (int j = 0; j < 4; ++j) {
            d_part[(size_t)blockIdx.x*128 + quad*4 + j]      = red[0][quad][j];
            d_part[(size_t)blockIdx.x*128 + 64 + quad*4 + j] = red[0][quad][4+j];
        }
    }
}

// ---------------- L7: w1 = relu(bn1(r)) @ ww1 + bw1, plus partial stats (8 ch) ----------------
__global__ __launch_bounds__(256) void w1_kernel(
    const float* __restrict__ g1, const float* __restrict__ bt1,
    const float* __restrict__ ww1, const float* __restrict__ bw1)
{
    int t = threadIdx.x;
    int rw = t >> 3, j = t & 7;
    __shared__ float rS[32][65];
    __shared__ float ww1s[64][8];
    __shared__ float bn1[256];
    __shared__ float bw1s[8];
    if (t < 64) {
        bn1[t]       = d_stats[8 + t];
        bn1[64 + t]  = d_stats[72 + t];
        bn1[128 + t] = g1[t];
        bn1[192 + t] = bt1[t];
    }
    if (t < 8) bw1s[t] = bw1[t];
    for (int i = t; i < 512; i += 256) ww1s[i>>3][i&7] = ww1[i];
    __syncthreads();

    float sj = 0.f, qj = 0.f;
    for (int it = 0; it < 16; ++it) {
        size_t rowbase = (size_t)blockIdx.x*512 + it*32;
        __syncthreads();
        for (int i = t; i < 2048; i += 256) {
            int r = i >> 6, c = i & 63;
            float v = d_rr[(rowbase + r)*64 + c];
            v = fmaxf((v - bn1[c])*bn1[64+c]*bn1[128+c] + bn1[192+c], 0.f);
            rS[r][c] = v;
        }
        __syncthreads();
        float acc = bw1s[j];
        #pragma unroll 8
        for (int c = 0; c < 64; ++c) acc += rS[rw][c] * ww1s[c][j];
        d_w1[(rowbase + rw)*8 + j] = acc;
        sj += acc; qj += acc*acc;
    }
    __shared__ float red2[32][8][2];
    red2[rw][j][0] = sj; red2[rw][j][1] = qj;
    __syncthreads();
    for (int st = 16; st; st >>= 1) {
        if (rw < st) {
            red2[rw][j][0] += red2[rw+st][j][0];
            red2[rw][j][1] += red2[rw+st][j][1];
        }
        __syncthreads();
    }
    if (rw == 0) {
        d_part[(size_t)blockIdx.x*16 + j]     = red2[0][j][0];
        d_part[(size_t)blockIdx.x*16 + 8 + j] = red2[0][j][1];
    }
}

// ---------------- L9: w2, softmax, combine (p_r recomputed from d_h) ----------
__global__ __launch_bounds__(256) void final_kernel(
    const float* __restrict__ g2, const float* __restrict__ bt2,
    const float* __restrict__ ww2, const float* __restrict__ bw2,
    const float* __restrict__ gp, const float* __restrict__ btp,
    const float* __restrict__ wp2, const float* __restrict__ bp2,
    float* __restrict__ out)
{
    int t = threadIdx.x, w = t >> 5, l = t & 31;
    int n = blockIdx.x*8 + w;
    __shared__ float ww2s[64];
    __shared__ float prm[32];
    __shared__ float bw2s[8];
    __shared__ float wsh[8][16][8];
    __shared__ float inv[8][8];
    __shared__ float wp2s[3][64];
    __shared__ float bp2s[64];
    __shared__ float bnp[12];
    if (t < 64) ww2s[t] = ww2[t];
    if (t < 8) {
        prm[t]      = d_stats[136 + t];
        prm[8 + t]  = d_stats[144 + t];
        prm[16 + t] = g2[t];
        prm[24 + t] = bt2[t];
        bw2s[t]     = bw2[t];
    }
    if (t >= 64 && t < 256) wp2s[(t-64)/64][(t-64)%64] = wp2[t-64];
    if (t >= 8 && t < 72) bp2s[t-8] = bp2[t-8];
    if (t >= 72 && t < 78)  bnp[t-72] = d_stats[t-72];
    if (t >= 78 && t < 81)  bnp[t-72] = gp[t-78];
    if (t >= 81 && t < 84)  bnp[t-72] = btp[t-81];
    __syncthreads();

    #pragma unroll
    for (int rep = 0; rep < 4; ++rep) {
        int e = rep*32 + l;
        int tt = e >> 3, j = e & 7;
        const float* w1row = &d_w1[((size_t)n*16 + tt)*8];
        float acc = bw2s[j];
        #pragma unroll
        for (int c = 0; c < 8; ++c) {
            float v = fmaxf((w1row[c] - prm[c])*prm[8+c]*prm[16+c] + prm[24+c], 0.f);
            acc += v * ww2s[c*8 + j];
        }
        wsh[w][tt][j] = acc;
    }
    __syncwarp();
    if (l < 8) {
        float m = -3.4e38f;
        #pragma unroll
        for (int tt = 0; tt < 16; ++tt) m = fmaxf(m, wsh[w][tt][l]);
        float ssum = 0.f;
        #pragma unroll
        for (int tt = 0; tt < 16; ++tt) {
            float e_ = expf(wsh[w][tt][l] - m);
            wsh[w][tt][l] = e_;
            ssum += e_;
        }
        inv[w][l] = 1.f / ssum;
    }
    __syncwarp();
    int j = l & 7;
    float acc0 = 0.f, acc1 = 0.f;
    const int* idxr = &d_idxv[(size_t)n*16];
    #pragma unroll
    for (int tt = 0; tt < 16; ++tt) {
        int gi = idxr[tt];
        float wt = wsh[w][tt][j];
        size_t row = (size_t)n*16 + tt;
        float h0 = d_h[row*3+0], h1 = d_h[row*3+1], h2 = d_h[row*3+2];
        h0 = fmaxf((h0 - bnp[0])*bnp[3]*bnp[6] + bnp[9],  0.f);
        h1 = fmaxf((h1 - bnp[1])*bnp[4]*bnp[7] + bnp[10], 0.f);
        h2 = fmaxf((h2 - bnp[2])*bnp[5]*bnp[8] + bnp[11], 0.f);
        float pr0 = bp2s[l]    + h0*wp2s[0][l]    + h1*wp2s[1][l]    + h2*wp2s[2][l];
        float pr1 = bp2s[32+l] + h0*wp2s[0][32+l] + h1*wp2s[1][32+l] + h2*wp2s[2][32+l];
        acc0 += (d_xv[(size_t)gi*64 + l]      + pr0) * wt;
        acc1 += (d_xv[(size_t)gi*64 + 32 + l] + pr1) * wt;
    }
    float iv = inv[w][j];
    out[(size_t)n*64 + l]      = acc0 * iv;
    out[(size_t)n*64 + 32 + l] = acc1 * iv;
}

// ---------------- launch ----------------
extern "C" void kernel_launch(void* const* d_in, const int* in_sizes, int n_in,
                              void* d_out, int out_size)
{
    const float* p   = (const float*)d_in[0];
    const float* x   = (const float*)d_in[1];
    // d_in[2] = o (batch sizes, structurally fixed -> unused)
    const float* wq  = (const float*)d_in[3];  const float* bq  = (const float*)d_in[4];
    const float* wk  = (const float*)d_in[5];  const float* bk  = (const float*)d_in[6];
    const float* wv  = (const float*)d_in[7];  const float* bv  = (const float*)d_in[8];
    const float* wp1 = (const float*)d_in[9];  const float* bp1 = (const float*)d_in[10];
    const float* gp  = (const float*)d_in[11]; const float* btp = (const float*)d_in[12];
    const float* wp2 = (const float*)d_in[13]; const float* bp2 = (const float*)d_in[14];
    const float* g1  = (const float*)d_in[15]; const float* bt1 = (const float*)d_in[16];
    const float* ww1 = (const float*)d_in[17]; const float* bw1 = (const float*)d_in[18];
    const float* g2  = (const float*)d_in[19]; const float* bt2 = (const float*)d_in[20];
    const float* ww2 = (const float*)d_in[21]; const float* bw2 = (const float*)d_in[22];
    float* out = (float*)d_out;

    cudaFuncSetAttribute(knn_kernel, cudaFuncAttributeMaxDynamicSharedMemorySize,
                         KNN_SMEM_BYTES);

    qkv_kernel<<<2048, 256>>>(x, wq, bq, wk, bk, wv, bv);   // launch 1
    sq_kernel<<<4096, 256>>>();                             // launch 2
    noop_kernel<<<1, 32>>>();                               // launch 3 (ncu alignment)
    dim3 kg(32, 8, 2);
    knn_kernel<<<kg, 256, KNN_SMEM_BYTES>>>();              // launch 4 <- profiled
    hstats_kernel<<<512, 256>>>(p, wp1, bp1);
    finalize_kernel<<<1, 256>>>(3, 512, 0);
    r_kernel<<<1024, 256>>>(gp, btp, wp2, bp2);
    finalize_kernel<<<1, 256>>>(64, 1024, 8);
    w1_kernel<<<1024, 256>>>(g1, bt1, ww1, bw1);
    finalize_kernel<<<1, 256>>>(8, 1024, 136);
    final_kernel<<<4096, 256>>>(g2, bt2, ww2, bw2, gp, btp, wp2, bp2, out);
}

// round 11
// speedup vs baseline: 2.4918x; 1.3096x over previous
#include <cuda_runtime.h>
#include <cuda_bf16.h>
#include <mma.h>
#include <math.h>
#include <stdint.h>

using namespace nvcuda;

// Problem constants
#define BATCH   8
#define NPB     4096
#define NPTS    (BATCH*NPB)      // 32768
#define KNN     16
#define CF      64
#define NKROWS  (NPTS*KNN)       // 524288
#define HDIM    8

// ---------------- scratch (device globals; no allocation) ----------------
__device__ float d_xq[NPTS*CF];
__device__ float d_xk[NPTS*CF];
__device__ float d_xv[NPTS*CF];
__device__ alignas(16) __nv_bfloat16 d_kh[NPTS*CF];
__device__ alignas(16) __nv_bfloat16 d_km[NPTS*CF];
__device__ alignas(16) __nv_bfloat16 d_kl[NPTS*CF];
__device__ alignas(16) __nv_bfloat16 d_vh[NPTS*CF];
__device__ alignas(16) __nv_bfloat16 d_vm[NPTS*CF];
__device__ alignas(16) __nv_bfloat16 d_vl[NPTS*CF];
__device__ float d_sqk[NPTS];
__device__ float d_sqv[NPTS];
__device__ int   d_idxk[NKROWS];
__device__ int   d_idxv[NKROWS];
__device__ float d_h[NKROWS*3];
__device__ float d_rr[(size_t)NKROWS*CF];   // 128 MB
__device__ float d_w1[NKROWS*HDIM];
__device__ float d_part[1024*128];
// stats: [0..2] mean_h, [3..5] rstd_h, [8..71] mean_r, [72..135] rstd_r,
//        [136..143] mean_w, [144..151] rstd_w
__device__ float d_stats[160];

// ---------------- no-op (profiling launch-index alignment) ----------------
__global__ void noop_kernel() {}

// ---------------- L1: q/k/v projections ----------------
__global__ __launch_bounds__(256) void qkv_kernel(
    const float* __restrict__ x,
    const float* __restrict__ wq, const float* __restrict__ bq,
    const float* __restrict__ wk, const float* __restrict__ bk,
    const float* __restrict__ wv, const float* __restrict__ bv)
{
    __shared__ float xs[16][64];
    __shared__ float ws[64][64];
    int t = threadIdx.x;
    int row = t >> 4, quad = t & 15;
    int rbase = blockIdx.x * 16;
    for (int i = t; i < 16*64; i += 256)
        xs[i>>6][i&63] = x[(size_t)(rbase + (i>>6))*64 + (i&63)];

    for (int m = 0; m < 3; ++m) {
        const float* W = (m==0) ? wq : (m==1) ? wk : wv;
        const float* Bv = (m==0) ? bq : (m==1) ? bk : bv;
        float* O = (m==0) ? d_xq : (m==1) ? d_xk : d_xv;
        __syncthreads();
        for (int i = t; i < 64*64; i += 256) ws[i>>6][i&63] = W[i];
        __syncthreads();
        float a0 = Bv[quad*4+0], a1 = Bv[quad*4+1], a2 = Bv[quad*4+2], a3 = Bv[quad*4+3];
        #pragma unroll 8
        for (int i = 0; i < 64; ++i) {
            float xv_ = xs[row][i];
            float4 w4 = *(const float4*)&ws[i][quad*4];
            a0 += xv_*w4.x; a1 += xv_*w4.y; a2 += xv_*w4.z; a3 += xv_*w4.w;
        }
        float4 o4; o4.x=a0; o4.y=a1; o4.z=a2; o4.w=a3;
        *(float4*)&O[(size_t)(rbase+row)*64 + quad*4] = o4;
    }
}

// ---------------- L1b: bf16 3-way split + squared norms ----------------
__global__ __launch_bounds__(256) void split_kernel()
{
    int w = threadIdx.x >> 5, l = threadIdx.x & 31;
    int row = blockIdx.x*8 + w;
    #pragma unroll
    for (int m = 0; m < 2; ++m) {
        const float* src = m ? d_xv : d_xk;
        __nv_bfloat16* Hd = m ? d_vh : d_kh;
        __nv_bfloat16* Md = m ? d_vm : d_km;
        __nv_bfloat16* Ld = m ? d_vl : d_kl;
        float* sq = m ? d_sqv : d_sqk;
        float a0 = src[(size_t)row*64 + 2*l];
        float a1 = src[(size_t)row*64 + 2*l + 1];
        float s = a0*a0 + a1*a1;
        #pragma unroll
        for (int o = 16; o; o >>= 1) s += __shfl_xor_sync(0xffffffffu, s, o);
        if (l == 0) sq[row] = s;
        __nv_bfloat16 h0 = __float2bfloat16(a0), h1 = __float2bfloat16(a1);
        float r0 = a0 - __bfloat162float(h0), r1 = a1 - __bfloat162float(h1);
        __nv_bfloat16 m0 = __float2bfloat16(r0), m1 = __float2bfloat16(r1);
        float q0 = r0 - __bfloat162float(m0), q1 = r1 - __bfloat162float(m1);
        __nv_bfloat16 l0 = __float2bfloat16(q0), l1 = __float2bfloat16(q1);
        ((__nv_bfloat162*)Hd)[(size_t)row*32 + l] = __nv_bfloat162(h0, h1);
        ((__nv_bfloat162*)Md)[(size_t)row*32 + l] = __nv_bfloat162(m0, m1);
        ((__nv_bfloat162*)Ld)[(size_t)row*32 + l] = __nv_bfloat162(l0, l1);
    }
}

// ---------------- L2: wmma (HMMA) distance GEMM + top-16 KNN ----------------
// grid (32, 8, 2): x = 128-query tile, y = batch, z = space (0:k, 1:v)
// smem: sQ 3x128x72 bf16 = 55296B, sC 2buf x 3x32x72 bf16 = 27648B,
//       sD 8 warps x 16x40 f32 = 20480B, sqC 2x32 f32 = 256B  -> 103680B
#define KNN_SMEM_BYTES 103680

// strict-less insert (valid while candidate idx strictly increases)
#define INS_STRICT(dd, ci) do {                                       \
    float _d = (dd);                                                  \
    if (_d < listD[15]) {                                             \
        float cd = _d; int cix = (ci);                                \
        _Pragma("unroll")                                             \
        for (int e = 0; e < 16; ++e) {                                \
            bool bt = cd < listD[e];                                  \
            float od = listD[e]; int oi = listI[e];                   \
            if (bt) { listD[e] = cd; listI[e] = cix; cd = od; cix = oi; } \
        }                                                             \
    }                                                                 \
} while (0)

__global__ __launch_bounds__(256) void knn_kernel()
{
    extern __shared__ char sm[];
    __nv_bfloat16* sQ = (__nv_bfloat16*)sm;               // [3][128][72]
    __nv_bfloat16* sC = (__nv_bfloat16*)(sm + 55296);     // [2][3][32][72]
    float* sD   = (float*)(sm + 82944);                   // [8][16][40]
    float* sqCs = (float*)(sm + 103424);                  // [2][32]

    const int sp = blockIdx.z;
    const __nv_bfloat16* fH = sp ? d_vh : d_kh;
    const __nv_bfloat16* fM = sp ? d_vm : d_km;
    const __nv_bfloat16* fL = sp ? d_vl : d_kl;
    const float* sqA  = sp ? d_sqv : d_sqk;
    int*         outIx = sp ? d_idxv : d_idxk;
    const int batch = blockIdx.y;
    const int qbase = batch*NPB + blockIdx.x*128;

    const int t = threadIdx.x;
    const int w = t >> 5, lid = t & 31;
    const int qi = lid >> 1, hh = lid & 1;   // scan roles

    // ---- load Q tiles (3 splits x 128 rows x 8 float4, ld=72) ----
    for (int i = t; i < 3072; i += 256) {
        int s = i >> 10, rem = i & 1023;
        int row = rem >> 3, f8 = rem & 7;
        const __nv_bfloat16* src = (s==0) ? fH : (s==1) ? fM : fL;
        float4 g = *(const float4*)&src[(size_t)(qbase + row)*64 + f8*8];
        *(float4*)&sQ[s*9216 + row*72 + f8*8] = g;
    }
    // ---- load candidate tile 0 (3 splits x 32 rows x 8 float4) ----
    for (int i = t; i < 768; i += 256) {
        int s = i >> 8, rem = i & 255;
        int row = rem >> 3, f8 = rem & 7;
        const __nv_bfloat16* src = (s==0) ? fH : (s==1) ? fM : fL;
        float4 g = *(const float4*)&src[(size_t)(batch*NPB + row)*64 + f8*8];
        *(float4*)&sC[s*2304 + row*72 + f8*8] = g;
    }
    if (t < 32) sqCs[t] = sqA[batch*NPB + t];
    __syncthreads();

    // ---- cache all A fragments (3 splits x 4 k-steps) in registers ----
    wmma::fragment<wmma::matrix_a, 16,16,16, __nv_bfloat16, wmma::row_major> Af[3][4];
    #pragma unroll
    for (int s = 0; s < 3; ++s)
        #pragma unroll
        for (int k = 0; k < 4; ++k)
            wmma::load_matrix_sync(Af[s][k], sQ + s*9216 + (w*16)*72 + k*16, 72);

    float listD[16]; int listI[16];
    #pragma unroll
    for (int e = 0; e < 16; ++e) { listD[e] = 3.4e38f; listI[e] = 0x7fffffff; }

    float* wd = sD + w*640;   // 16x40 per-warp dist staging

    for (int tile = 0; tile < 128; ++tile) {
        const int buf = tile & 1;
        const int cbase = batch*NPB + tile*32;

        // prefetch next tile into registers (hidden behind MMA)
        float4 pf0, pf1, pf2; float pfsq = 0.f;
        int s0=0, r0_=0, f80=0, s1=0, r1_=0, f81=0, s2=0, r2_=0, f82=0;
        if (tile + 1 < 128) {
            const int nb = cbase + 32;
            int i0 = t;        s0 = i0 >> 8; r0_ = (i0 & 255) >> 3; f80 = i0 & 7;
            int i1 = t + 256;  s1 = i1 >> 8; r1_ = (i1 & 255) >> 3; f81 = i1 & 7;
            int i2 = t + 512;  s2 = i2 >> 8; r2_ = (i2 & 255) >> 3; f82 = i2 & 7;
            const __nv_bfloat16* p0 = (s0==0) ? fH : (s0==1) ? fM : fL;
            const __nv_bfloat16* p1 = (s1==0) ? fH : (s1==1) ? fM : fL;
            const __nv_bfloat16* p2 = (s2==0) ? fH : (s2==1) ? fM : fL;
            pf0 = *(const float4*)&p0[(size_t)(nb + r0_)*64 + f80*8];
            pf1 = *(const float4*)&p1[(size_t)(nb + r1_)*64 + f81*8];
            pf2 = *(const float4*)&p2[(size_t)(nb + r2_)*64 + f82*8];
            if (t < 32) pfsq = sqA[nb + t];
        }

        // ---- 6-term bf16-split MMA: D = Q . C^T (16q x 32c per warp) ----
        wmma::fragment<wmma::accumulator, 16,16,16, float> Cf0, Cf1;
        wmma::fill_fragment(Cf0, 0.0f);
        wmma::fill_fragment(Cf1, 0.0f);
        const __nv_bfloat16* cb = sC + buf*6912;
        #pragma unroll
        for (int k = 0; k < 4; ++k) {
            wmma::fragment<wmma::matrix_b, 16,16,16, __nv_bfloat16, wmma::col_major> B0, B1;
            // B = hi: terms hh, mh, lh
            wmma::load_matrix_sync(B0, cb + k*16, 72);
            wmma::load_matrix_sync(B1, cb + 16*72 + k*16, 72);
            wmma::mma_sync(Cf0, Af[0][k], B0, Cf0);
            wmma::mma_sync(Cf1, Af[0][k], B1, Cf1);
            wmma::mma_sync(Cf0, Af[1][k], B0, Cf0);
            wmma::mma_sync(Cf1, Af[1][k], B1, Cf1);
            wmma::mma_sync(Cf0, Af[2][k], B0, Cf0);
            wmma::mma_sync(Cf1, Af[2][k], B1, Cf1);
            // B = mid: terms hm, mm
            wmma::load_matrix_sync(B0, cb + 2304 + k*16, 72);
            wmma::load_matrix_sync(B1, cb + 2304 + 16*72 + k*16, 72);
            wmma::mma_sync(Cf0, Af[0][k], B0, Cf0);
            wmma::mma_sync(Cf1, Af[0][k], B1, Cf1);
            wmma::mma_sync(Cf0, Af[1][k], B0, Cf0);
            wmma::mma_sync(Cf1, Af[1][k], B1, Cf1);
            // B = lo: term hl
            wmma::load_matrix_sync(B0, cb + 4608 + k*16, 72);
            wmma::load_matrix_sync(B1, cb + 4608 + 16*72 + k*16, 72);
            wmma::mma_sync(Cf0, Af[0][k], B0, Cf0);
            wmma::mma_sync(Cf1, Af[0][k], B1, Cf1);
        }
        wmma::store_matrix_sync(wd,      Cf0, 40, wmma::mem_row_major);
        wmma::store_matrix_sync(wd + 16, Cf1, 40, wmma::mem_row_major);
        __syncwarp();

        // ---- scan: 2 threads/query, 16 cands each; key = sqC - 2*dot ----
        const float* rowp = wd + qi*40 + hh*16;
        const float* sqb  = sqCs + buf*32 + hh*16;
        const int cbg = cbase + hh*16;
        #pragma unroll
        for (int g = 0; g < 4; ++g) {
            float4 dv = *(const float4*)(rowp + g*4);
            float d0 = fmaf(-2.f, dv.x, sqb[g*4+0]);
            float d1 = fmaf(-2.f, dv.y, sqb[g*4+1]);
            float d2 = fmaf(-2.f, dv.z, sqb[g*4+2]);
            float d3 = fmaf(-2.f, dv.w, sqb[g*4+3]);
            float mn = fminf(fminf(d0, d1), fminf(d2, d3));
            if (mn < listD[15]) {
                INS_STRICT(d0, cbg+g*4+0); INS_STRICT(d1, cbg+g*4+1);
                INS_STRICT(d2, cbg+g*4+2); INS_STRICT(d3, cbg+g*4+3);
            }
        }

        // ---- commit prefetched tile ----
        if (tile + 1 < 128) {
            __nv_bfloat16* dst = sC + (1-buf)*6912;
            *(float4*)&dst[s0*2304 + r0_*72 + f80*8] = pf0;
            *(float4*)&dst[s1*2304 + r1_*72 + f81*8] = pf1;
            *(float4*)&dst[s2*2304 + r2_*72 + f82*8] = pf2;
            if (t < 32) sqCs[(1-buf)*32 + t] = pfsq;
        }
        __syncthreads();
    }

    // ---- merge the two 16-lists per query (reuse dead Q smem) ----
    float* mD = (float*)sm;
    int*   mI = (int*)(sm + 16384);
    const int q = w*16 + qi;
    #pragma unroll
    for (int e = 0; e < 16; ++e) {
        mD[q*32 + hh*16 + e] = listD[e];
        mI[q*32 + hh*16 + e] = listI[e];
    }
    __syncthreads();
    if (hh == 0) {
        #pragma unroll
        for (int e = 0; e < 16; ++e) {
            float dd = mD[q*32 + 16 + e];
            int   ci = mI[q*32 + 16 + e];
            if (dd < listD[15] || (dd == listD[15] && ci < listI[15])) {
                float cd = dd; int cix = ci;
                #pragma unroll
                for (int e2 = 0; e2 < 16; ++e2) {
                    bool bt = (cd < listD[e2]) || (cd == listD[e2] && cix < listI[e2]);
                    float od = listD[e2]; int oi = listI[e2];
                    if (bt) { listD[e2] = cd; listI[e2] = cix; cd = od; cix = oi; }
                }
            }
        }
        int gq = qbase + q;
        #pragma unroll
        for (int e = 0; e < 16; ++e) outIx[(size_t)gq*16 + e] = listI[e];
    }
}

// ---------------- L3: h = p_rel @ wp1 + bp1, plus partial stats (3 ch) ----------------
__global__ __launch_bounds__(256) void hstats_kernel(
    const float* __restrict__ p, const float* __restrict__ wp1, const float* __restrict__ bp1)
{
    int t = threadIdx.x;
    float w[9];
    #pragma unroll
    for (int j = 0; j < 9; ++j) w[j] = wp1[j];
    float b0 = bp1[0], b1 = bp1[1], b2 = bp1[2];
    float s0=0,s1=0,s2=0,q0=0,q1=0,q2=0;
    for (int rep = 0; rep < 4; ++rep) {
        int row = blockIdx.x*1024 + rep*256 + t;
        int n = row >> 4;
        int gi = d_idxk[row];
        float r0 = p[(size_t)gi*3+0] - p[(size_t)n*3+0];
        float r1 = p[(size_t)gi*3+1] - p[(size_t)n*3+1];
        float r2 = p[(size_t)gi*3+2] - p[(size_t)n*3+2];
        float h0 = r0*w[0] + r1*w[3] + r2*w[6] + b0;
        float h1 = r0*w[1] + r1*w[4] + r2*w[7] + b1;
        float h2 = r0*w[2] + r1*w[5] + r2*w[8] + b2;
        d_h[(size_t)row*3+0] = h0; d_h[(size_t)row*3+1] = h1; d_h[(size_t)row*3+2] = h2;
        s0 += h0; s1 += h1; s2 += h2;
        q0 += h0*h0; q1 += h1*h1; q2 += h2*h2;
    }
    __shared__ float red[6][256];
    red[0][t]=s0; red[1][t]=s1; red[2][t]=s2; red[3][t]=q0; red[4][t]=q1; red[5][t]=q2;
    __syncthreads();
    for (int st = 128; st; st >>= 1) {
        if (t < st) {
            #pragma unroll
            for (int e = 0; e < 6; ++e) red[e][t] += red[e][t+st];
        }
        __syncthreads();
    }
    if (t < 6) d_part[blockIdx.x*6 + t] = red[t][0];
}

// ---------------- generic deterministic finalize (mean / rstd) ----------------
__global__ __launch_bounds__(256) void finalize_kernel(int nch, int nblocks, int statOff)
{
    __shared__ double sh[512];
    int t = threadIdx.x;
    int nsl = 256 / nch;
    int c = t % nch, sl = t / nch;
    double s = 0.0, q = 0.0;
    if (sl < nsl) {
        for (int b = sl; b < nblocks; b += nsl) {
            s += (double)d_part[(size_t)b*2*nch + c];
            q += (double)d_part[(size_t)b*2*nch + nch + c];
        }
    }
    sh[t] = s; sh[256 + t] = q;
    __syncthreads();
    if (t < nch) {
        double S = 0.0, Q = 0.0;
        for (int s2 = 0; s2 < nsl; ++s2) { S += sh[s2*nch + t]; Q += sh[256 + s2*nch + t]; }
        double cnt = (double)NKROWS;
        double m = S / cnt;
        double v = Q / cnt - m*m;
        d_stats[statOff + t]        = (float)m;
        d_stats[statOff + nch + t]  = (float)(1.0 / sqrt(v + 1e-5));
    }
}

// ---------------- L5: r = xk_g - xq + p_r, plus partial stats over r (64 ch) -----
__global__ __launch_bounds__(256) void r_kernel(
    const float* __restrict__ gp, const float* __restrict__ btp,
    const float* __restrict__ wp2, const float* __restrict__ bp2)
{
    int t = threadIdx.x;
    int rl = t >> 4, quad = t & 15;
    __shared__ float wp2s[3][64];
    __shared__ float bp2s[64];
    __shared__ float bnp[12];
    if (t < 192) wp2s[t/64][t%64] = wp2[t];
    if (t < 64)  bp2s[t] = bp2[t];
    if (t < 6)   bnp[t] = d_stats[t];
    if (t >= 6 && t < 9)   bnp[t] = gp[t-6];
    if (t >= 9 && t < 12)  bnp[t] = btp[t-9];
    __syncthreads();

    float4 w0 = *(const float4*)&wp2s[0][quad*4];
    float4 w1 = *(const float4*)&wp2s[1][quad*4];
    float4 w2 = *(const float4*)&wp2s[2][quad*4];
    float4 bp4 = *(const float4*)&bp2s[quad*4];
    float sx=0,sy=0,sz=0,sw=0, qx=0,qy=0,qz=0,qw=0;

    for (int it = 0; it < 32; ++it) {
        size_t row = (size_t)blockIdx.x*512 + it*16 + rl;
        float h0 = d_h[row*3+0], h1 = d_h[row*3+1], h2 = d_h[row*3+2];
        h0 = fmaxf((h0 - bnp[0])*bnp[3]*bnp[6] + bnp[9],  0.f);
        h1 = fmaxf((h1 - bnp[1])*bnp[4]*bnp[7] + bnp[10], 0.f);
        h2 = fmaxf((h2 - bnp[2])*bnp[5]*bnp[8] + bnp[11], 0.f);
        float4 pr;
        pr.x = bp4.x + h0*w0.x + h1*w1.x + h2*w2.x;
        pr.y = bp4.y + h0*w0.y + h1*w1.y + h2*w2.y;
        pr.z = bp4.z + h0*w0.z + h1*w1.z + h2*w2.z;
        pr.w = bp4.w + h0*w0.w + h1*w1.w + h2*w2.w;
        int n  = (int)(row >> 4);
        int gi = d_idxk[row];
        float4 xk4 = *(const float4*)&d_xk[(size_t)gi*64 + quad*4];
        float4 xq4 = *(const float4*)&d_xq[(size_t)n*64 + quad*4];
        float4 r4;
        r4.x = xk4.x - xq4.x + pr.x;
        r4.y = xk4.y - xq4.y + pr.y;
        r4.z = xk4.z - xq4.z + pr.z;
        r4.w = xk4.w - xq4.w + pr.w;
        *(float4*)&d_rr[row*64 + quad*4] = r4;
        sx += r4.x; sy += r4.y; sz += r4.z; sw += r4.w;
        qx += r4.x*r4.x; qy += r4.y*r4.y; qz += r4.z*r4.z; qw += r4.w*r4.w;
    }
    __shared__ float red[16][16][8];
    red[rl][quad][0]=sx; red[rl][quad][1]=sy; red[rl][quad][2]=sz; red[rl][quad][3]=sw;
    red[rl][quad][4]=qx; red[rl][quad][5]=qy; red[rl][quad][6]=qz; red[rl][quad][7]=qw;
    __syncthreads();
    for (int st = 8; st; st >>= 1) {
        if (rl < st) {
            #pragma unroll
            for (int e = 0; e < 8; ++e) red[rl][quad][e] += red[rl+st][quad][e];
        }
        __syncthreads();
    }
    if (rl == 0) {
        #pragma unroll
        for (int j = 0; j < 4; ++j) {
            d_part[(size_t)blockIdx.x*128 + quad*4 + j]      = red[0][quad][j];
            d_part[(size_t)blockIdx.x*128 + 64 + quad*4 + j] = red[0][quad][4+j];
        }
    }
}

// ---------------- L7: w1 = relu(bn1(r)) @ ww1 + bw1, plus partial stats (8 ch) ----------------
__global__ __launch_bounds__(256) void w1_kernel(
    const float* __restrict__ g1, const float* __restrict__ bt1,
    const float* __restrict__ ww1, const float* __restrict__ bw1)
{
    int t = threadIdx.x;
    int rw = t >> 3, j = t & 7;
    __shared__ float rS[32][65];
    __shared__ float ww1s[64][8];
    __shared__ float bn1[256];
    __shared__ float bw1s[8];
    if (t < 64) {
        bn1[t]       = d_stats[8 + t];
        bn1[64 + t]  = d_stats[72 + t];
        bn1[128 + t] = g1[t];
        bn1[192 + t] = bt1[t];
    }
    if (t < 8) bw1s[t] = bw1[t];
    for (int i = t; i < 512; i += 256) ww1s[i>>3][i&7] = ww1[i];
    __syncthreads();

    float sj = 0.f, qj = 0.f;
    for (int it = 0; it < 16; ++it) {
        size_t rowbase = (size_t)blockIdx.x*512 + it*32;
        __syncthreads();
        for (int i = t; i < 2048; i += 256) {
            int r = i >> 6, c = i & 63;
            float v = d_rr[(rowbase + r)*64 + c];
            v = fmaxf((v - bn1[c])*bn1[64+c]*bn1[128+c] + bn1[192+c], 0.f);
            rS[r][c] = v;
        }
        __syncthreads();
        float acc = bw1s[j];
        #pragma unroll 8
        for (int c = 0; c < 64; ++c) acc += rS[rw][c] * ww1s[c][j];
        d_w1[(rowbase + rw)*8 + j] = acc;
        sj += acc; qj += acc*acc;
    }
    __shared__ float red2[32][8][2];
    red2[rw][j][0] = sj; red2[rw][j][1] = qj;
    __syncthreads();
    for (int st = 16; st; st >>= 1) {
        if (rw < st) {
            red2[rw][j][0] += red2[rw+st][j][0];
            red2[rw][j][1] += red2[rw+st][j][1];
        }
        __syncthreads();
    }
    if (rw == 0) {
        d_part[(size_t)blockIdx.x*16 + j]     = red2[0][j][0];
        d_part[(size_t)blockIdx.x*16 + 8 + j] = red2[0][j][1];
    }
}

// ---------------- L9: w2, softmax, combine (p_r recomputed from d_h) ----------
__global__ __launch_bounds__(256) void final_kernel(
    const float* __restrict__ g2, const float* __restrict__ bt2,
    const float* __restrict__ ww2, const float* __restrict__ bw2,
    const float* __restrict__ gp, const float* __restrict__ btp,
    const float* __restrict__ wp2, const float* __restrict__ bp2,
    float* __restrict__ out)
{
    int t = threadIdx.x, w = t >> 5, l = t & 31;
    int n = blockIdx.x*8 + w;
    __shared__ float ww2s[64];
    __shared__ float prm[32];
    __shared__ float bw2s[8];
    __shared__ float wsh[8][16][8];
    __shared__ float inv[8][8];
    __shared__ float wp2s[3][64];
    __shared__ float bp2s[64];
    __shared__ float bnp[12];
    if (t < 64) ww2s[t] = ww2[t];
    if (t < 8) {
        prm[t]      = d_stats[136 + t];
        prm[8 + t]  = d_stats[144 + t];
        prm[16 + t] = g2[t];
        prm[24 + t] = bt2[t];
        bw2s[t]     = bw2[t];
    }
    if (t >= 64 && t < 256) wp2s[(t-64)/64][(t-64)%64] = wp2[t-64];
    if (t >= 8 && t < 72) bp2s[t-8] = bp2[t-8];
    if (t >= 72 && t < 78)  bnp[t-72] = d_stats[t-72];
    if (t >= 78 && t < 81)  bnp[t-72] = gp[t-78];
    if (t >= 81 && t < 84)  bnp[t-72] = btp[t-81];
    __syncthreads();

    #pragma unroll
    for (int rep = 0; rep < 4; ++rep) {
        int e = rep*32 + l;
        int tt = e >> 3, j = e & 7;
        const float* w1row = &d_w1[((size_t)n*16 + tt)*8];
        float acc = bw2s[j];
        #pragma unroll
        for (int c = 0; c < 8; ++c) {
            float v = fmaxf((w1row[c] - prm[c])*prm[8+c]*prm[16+c] + prm[24+c], 0.f);
            acc += v * ww2s[c*8 + j];
        }
        wsh[w][tt][j] = acc;
    }
    __syncwarp();
    if (l < 8) {
        float m = -3.4e38f;
        #pragma unroll
        for (int tt = 0; tt < 16; ++tt) m = fmaxf(m, wsh[w][tt][l]);
        float ssum = 0.f;
        #pragma unroll
        for (int tt = 0; tt < 16; ++tt) {
            float e_ = expf(wsh[w][tt][l] - m);
            wsh[w][tt][l] = e_;
            ssum += e_;
        }
        inv[w][l] = 1.f / ssum;
    }
    __syncwarp();
    int j = l & 7;
    float acc0 = 0.f, acc1 = 0.f;
    const int* idxr = &d_idxv[(size_t)n*16];
    #pragma unroll
    for (int tt = 0; tt < 16; ++tt) {
        int gi = idxr[tt];
        float wt = wsh[w][tt][j];
        size_t row = (size_t)n*16 + tt;
        float h0 = d_h[row*3+0], h1 = d_h[row*3+1], h2 = d_h[row*3+2];
        h0 = fmaxf((h0 - bnp[0])*bnp[3]*bnp[6] + bnp[9],  0.f);
        h1 = fmaxf((h1 - bnp[1])*bnp[4]*bnp[7] + bnp[10], 0.f);
        h2 = fmaxf((h2 - bnp[2])*bnp[5]*bnp[8] + bnp[11], 0.f);
        float pr0 = bp2s[l]    + h0*wp2s[0][l]    + h1*wp2s[1][l]    + h2*wp2s[2][l];
        float pr1 = bp2s[32+l] + h0*wp2s[0][32+l] + h1*wp2s[1][32+l] + h2*wp2s[2][32+l];
        acc0 += (d_xv[(size_t)gi*64 + l]      + pr0) * wt;
        acc1 += (d_xv[(size_t)gi*64 + 32 + l] + pr1) * wt;
    }
    float iv = inv[w][j];
    out[(size_t)n*64 + l]      = acc0 * iv;
    out[(size_t)n*64 + 32 + l] = acc1 * iv;
}

// ---------------- launch ----------------
extern "C" void kernel_launch(void* const* d_in, const int* in_sizes, int n_in,
                              void* d_out, int out_size)
{
    const float* p   = (const float*)d_in[0];
    const float* x   = (const float*)d_in[1];
    // d_in[2] = o (batch sizes, structurally fixed -> unused)
    const float* wq  = (const float*)d_in[3];  const float* bq  = (const float*)d_in[4];
    const float* wk  = (const float*)d_in[5];  const float* bk  = (const float*)d_in[6];
    const float* wv  = (const float*)d_in[7];  const float* bv  = (const float*)d_in[8];
    const float* wp1 = (const float*)d_in[9];  const float* bp1 = (const float*)d_in[10];
    const float* gp  = (const float*)d_in[11]; const float* btp = (const float*)d_in[12];
    const float* wp2 = (const float*)d_in[13]; const float* bp2 = (const float*)d_in[14];
    const float* g1  = (const float*)d_in[15]; const float* bt1 = (const float*)d_in[16];
    const float* ww1 = (const float*)d_in[17]; const float* bw1 = (const float*)d_in[18];
    const float* g2  = (const float*)d_in[19]; const float* bt2 = (const float*)d_in[20];
    const float* ww2 = (const float*)d_in[21]; const float* bw2 = (const float*)d_in[22];
    float* out = (float*)d_out;

    cudaFuncSetAttribute(knn_kernel, cudaFuncAttributeMaxDynamicSharedMemorySize,
                         KNN_SMEM_BYTES);

    qkv_kernel<<<2048, 256>>>(x, wq, bq, wk, bk, wv, bv);   // launch 1
    split_kernel<<<4096, 256>>>();                          // launch 2
    noop_kernel<<<1, 32>>>();                               // launch 3 (ncu alignment)
    dim3 kg(32, 8, 2);
    knn_kernel<<<kg, 256, KNN_SMEM_BYTES>>>();              // launch 4 <- profiled
    hstats_kernel<<<512, 256>>>(p, wp1, bp1);
    finalize_kernel<<<1, 256>>>(3, 512, 0);
    r_kernel<<<1024, 256>>>(gp, btp, wp2, bp2);
    finalize_kernel<<<1, 256>>>(64, 1024, 8);
    w1_kernel<<<1024, 256>>>(g1, bt1, ww1, bw1);
    finalize_kernel<<<1, 256>>>(8, 1024, 136);
    final_kernel<<<4096, 256>>>(g2, bt2, ww2, bw2, gp, btp, wp2, bp2, out);
}

// round 12
// speedup vs baseline: 3.1789x; 1.2757x over previous
#include <cuda_runtime.h>
#include <cuda_bf16.h>
#include <mma.h>
#include <math.h>
#include <stdint.h>

using namespace nvcuda;

// Problem constants
#define BATCH   8
#define NPB     4096
#define NPTS    (BATCH*NPB)      // 32768
#define KNN     16
#define CF      64
#define NKROWS  (NPTS*KNN)       // 524288
#define HDIM    8

// ---------------- scratch (device globals; no allocation) ----------------
__device__ float d_xq[NPTS*CF];
__device__ float d_xk[NPTS*CF];
__device__ float d_xv[NPTS*CF];
__device__ alignas(16) __nv_bfloat16 d_kh[NPTS*CF];
__device__ alignas(16) __nv_bfloat16 d_km[NPTS*CF];
__device__ alignas(16) __nv_bfloat16 d_kl[NPTS*CF];
__device__ alignas(16) __nv_bfloat16 d_vh[NPTS*CF];
__device__ alignas(16) __nv_bfloat16 d_vm[NPTS*CF];
__device__ alignas(16) __nv_bfloat16 d_vl[NPTS*CF];
__device__ float d_sqk[NPTS];
__device__ float d_sqv[NPTS];
__device__ int   d_idxk[NKROWS];
__device__ int   d_idxv[NKROWS];
__device__ float d_h[NKROWS*3];
__device__ float d_rr[(size_t)NKROWS*CF];   // 128 MB
__device__ float d_w1[NKROWS*HDIM];
__device__ float d_part[1024*128];
// stats: [0..2] mean_h, [3..5] rstd_h, [8..71] mean_r, [72..135] rstd_r,
//        [136..143] mean_w, [144..151] rstd_w
__device__ float d_stats[160];

// ---------------- cp.async helpers ----------------
__device__ __forceinline__ uint32_t smem_u32(const void* p) {
    uint32_t a;
    asm("{ .reg .u64 t; cvta.to.shared.u64 t, %1; cvt.u32.u64 %0, t; }"
        : "=r"(a) : "l"(p));
    return a;
}
__device__ __forceinline__ void cp_async16(uint32_t dst, const void* src) {
    asm volatile("cp.async.cg.shared.global [%0], [%1], 16;" :: "r"(dst), "l"(src));
}
__device__ __forceinline__ void cp_async4(uint32_t dst, const void* src) {
    asm volatile("cp.async.ca.shared.global [%0], [%1], 4;" :: "r"(dst), "l"(src));
}
#define CP_COMMIT() asm volatile("cp.async.commit_group;" ::: "memory")
#define CP_WAIT0()  asm volatile("cp.async.wait_group 0;" ::: "memory")

// ---------------- no-op (profiling launch-index alignment) ----------------
__global__ void noop_kernel() {}

// ---------------- L1: q/k/v projections ----------------
__global__ __launch_bounds__(256) void qkv_kernel(
    const float* __restrict__ x,
    const float* __restrict__ wq, const float* __restrict__ bq,
    const float* __restrict__ wk, const float* __restrict__ bk,
    const float* __restrict__ wv, const float* __restrict__ bv)
{
    __shared__ float xs[16][64];
    __shared__ float ws[64][64];
    int t = threadIdx.x;
    int row = t >> 4, quad = t & 15;
    int rbase = blockIdx.x * 16;
    for (int i = t; i < 16*64; i += 256)
        xs[i>>6][i&63] = x[(size_t)(rbase + (i>>6))*64 + (i&63)];

    for (int m = 0; m < 3; ++m) {
        const float* W = (m==0) ? wq : (m==1) ? wk : wv;
        const float* Bv = (m==0) ? bq : (m==1) ? bk : bv;
        float* O = (m==0) ? d_xq : (m==1) ? d_xk : d_xv;
        __syncthreads();
        for (int i = t; i < 64*64; i += 256) ws[i>>6][i&63] = W[i];
        __syncthreads();
        float a0 = Bv[quad*4+0], a1 = Bv[quad*4+1], a2 = Bv[quad*4+2], a3 = Bv[quad*4+3];
        #pragma unroll 8
        for (int i = 0; i < 64; ++i) {
            float xv_ = xs[row][i];
            float4 w4 = *(const float4*)&ws[i][quad*4];
            a0 += xv_*w4.x; a1 += xv_*w4.y; a2 += xv_*w4.z; a3 += xv_*w4.w;
        }
        float4 o4; o4.x=a0; o4.y=a1; o4.z=a2; o4.w=a3;
        *(float4*)&O[(size_t)(rbase+row)*64 + quad*4] = o4;
    }
}

// ---------------- L1b: bf16 3-way split + squared norms ----------------
__global__ __launch_bounds__(256) void split_kernel()
{
    int w = threadIdx.x >> 5, l = threadIdx.x & 31;
    int row = blockIdx.x*8 + w;
    #pragma unroll
    for (int m = 0; m < 2; ++m) {
        const float* src = m ? d_xv : d_xk;
        __nv_bfloat16* Hd = m ? d_vh : d_kh;
        __nv_bfloat16* Md = m ? d_vm : d_km;
        __nv_bfloat16* Ld = m ? d_vl : d_kl;
        float* sq = m ? d_sqv : d_sqk;
        float a0 = src[(size_t)row*64 + 2*l];
        float a1 = src[(size_t)row*64 + 2*l + 1];
        float s = a0*a0 + a1*a1;
        #pragma unroll
        for (int o = 16; o; o >>= 1) s += __shfl_xor_sync(0xffffffffu, s, o);
        if (l == 0) sq[row] = s;
        __nv_bfloat16 h0 = __float2bfloat16(a0), h1 = __float2bfloat16(a1);
        float r0 = a0 - __bfloat162float(h0), r1 = a1 - __bfloat162float(h1);
        __nv_bfloat16 m0 = __float2bfloat16(r0), m1 = __float2bfloat16(r1);
        float q0 = r0 - __bfloat162float(m0), q1 = r1 - __bfloat162float(m1);
        __nv_bfloat16 l0 = __float2bfloat16(q0), l1 = __float2bfloat16(q1);
        ((__nv_bfloat162*)Hd)[(size_t)row*32 + l] = __nv_bfloat162(h0, h1);
        ((__nv_bfloat162*)Md)[(size_t)row*32 + l] = __nv_bfloat162(m0, m1);
        ((__nv_bfloat162*)Ld)[(size_t)row*32 + l] = __nv_bfloat162(l0, l1);
    }
}

// ---------------- L2: wmma (HMMA) distance GEMM + top-16 KNN (v5) ----------
// grid (32, 8, 2): x = 128-query tile, y = batch, z = space (0:k, 1:v)
// smem: sQ 3x128x72 bf16 = 55296B, sC 2buf x 3x32x72 bf16 = 27648B,
//       sD 8 warps x 16x40 f32 = 20480B, sqC 2x32 f32 = 256B  -> 103680B
// 2 CTAs/SM: 2x103680 = 207360B <= 228KB carveout; regs capped at 128.
#define KNN_SMEM_BYTES 103680

// strict-less insert (valid while candidate idx strictly increases)
#define INS_STRICT(dd, ci) do {                                       \
    float _d = (dd);                                                  \
    if (_d < listD[15]) {                                             \
        float cd = _d; int cix = (ci);                                \
        _Pragma("unroll")                                             \
        for (int e = 0; e < 16; ++e) {                                \
            bool bt = cd < listD[e];                                  \
            float od = listD[e]; int oi = listI[e];                   \
            if (bt) { listD[e] = cd; listI[e] = cix; cd = od; cix = oi; } \
        }                                                             \
    }                                                                 \
} while (0)

__global__ __launch_bounds__(256, 2) void knn_kernel()
{
    extern __shared__ char sm[];
    __nv_bfloat16* sQ = (__nv_bfloat16*)sm;               // [3][128][72]
    __nv_bfloat16* sC = (__nv_bfloat16*)(sm + 55296);     // [2][3][32][72]
    float* sD   = (float*)(sm + 82944);                   // [8][16][40]
    float* sqCs = (float*)(sm + 103424);                  // [2][32]

    const int sp = blockIdx.z;
    const __nv_bfloat16* fH = sp ? d_vh : d_kh;
    const __nv_bfloat16* fM = sp ? d_vm : d_km;
    const __nv_bfloat16* fL = sp ? d_vl : d_kl;
    const float* sqA  = sp ? d_sqv : d_sqk;
    int*         outIx = sp ? d_idxv : d_idxk;
    const int batch = blockIdx.y;
    const int qbase = batch*NPB + blockIdx.x*128;

    const int t = threadIdx.x;
    const int w = t >> 5, lid = t & 31;
    const int qi = lid >> 1, hh = lid & 1;   // scan roles

    // per-thread cp.async slot decomposition (3 x 16B per tile)
    const int i0 = t;        const int s0 = i0 >> 8, r0_ = (i0 & 255) >> 3, f80 = i0 & 7;
    const int i1 = t + 256;  const int s1 = i1 >> 8, r1_ = (i1 & 255) >> 3, f81 = i1 & 7;
    const int i2 = t + 512;  const int s2 = i2 >> 8, r2_ = (i2 & 255) >> 3, f82 = i2 & 7;
    const __nv_bfloat16* p0 = (s0==0) ? fH : (s0==1) ? fM : fL;
    const __nv_bfloat16* p1 = (s1==0) ? fH : (s1==1) ? fM : fL;
    const __nv_bfloat16* p2 = (s2==0) ? fH : (s2==1) ? fM : fL;
    const uint32_t scBase = smem_u32(sC);
    const uint32_t d0off = (uint32_t)(s0*2304 + r0_*72 + f80*8) * 2;
    const uint32_t d1off = (uint32_t)(s1*2304 + r1_*72 + f81*8) * 2;
    const uint32_t d2off = (uint32_t)(s2*2304 + r2_*72 + f82*8) * 2;
    const uint32_t sqBase = smem_u32(sqCs);

    // ---- load Q tiles (3 splits x 128 rows x 8 float4, ld=72) ----
    for (int i = t; i < 3072; i += 256) {
        int s = i >> 10, rem = i & 1023;
        int row = rem >> 3, f8 = rem & 7;
        const __nv_bfloat16* src = (s==0) ? fH : (s==1) ? fM : fL;
        float4 g = *(const float4*)&src[(size_t)(qbase + row)*64 + f8*8];
        *(float4*)&sQ[s*9216 + row*72 + f8*8] = g;
    }
    // ---- load candidate tile 0 (3 splits x 32 rows x 8 float4) ----
    for (int i = t; i < 768; i += 256) {
        int s = i >> 8, rem = i & 255;
        int row = rem >> 3, f8 = rem & 7;
        const __nv_bfloat16* src = (s==0) ? fH : (s==1) ? fM : fL;
        float4 g = *(const float4*)&src[(size_t)(batch*NPB + row)*64 + f8*8];
        *(float4*)&sC[s*2304 + row*72 + f8*8] = g;
    }
    if (t < 32) sqCs[t] = sqA[batch*NPB + t];
    __syncthreads();

    float listD[16]; int listI[16];
    #pragma unroll
    for (int e = 0; e < 16; ++e) { listD[e] = 3.4e38f; listI[e] = 0x7fffffff; }

    float* wd = sD + w*640;                 // 16x40 per-warp dist staging
    const __nv_bfloat16* aQ = sQ + (w*16)*72;  // this warp's query rows

    for (int tile = 0; tile < 128; ++tile) {
        const int buf = tile & 1;
        const int cbase = batch*NPB + tile*32;

        // async prefetch of next tile into the idle buffer
        if (tile + 1 < 128) {
            const int nb = cbase + 32;
            const uint32_t db = scBase + (uint32_t)(1-buf)*13824;
            cp_async16(db + d0off, &p0[(size_t)(nb + r0_)*64 + f80*8]);
            cp_async16(db + d1off, &p1[(size_t)(nb + r1_)*64 + f81*8]);
            cp_async16(db + d2off, &p2[(size_t)(nb + r2_)*64 + f82*8]);
            if (t < 32) cp_async4(sqBase + ((1-buf)*32 + t)*4, &sqA[nb + t]);
            CP_COMMIT();
        }

        // ---- 6-term bf16-split MMA: D = Q . C^T (16q x 32c per warp) ----
        // Per-accumulator (k, term) order identical to R10 -> bit-identical.
        wmma::fragment<wmma::accumulator, 16,16,16, float> Cf0, Cf1;
        wmma::fill_fragment(Cf0, 0.0f);
        wmma::fill_fragment(Cf1, 0.0f);
        const __nv_bfloat16* cb = sC + buf*6912;
        #pragma unroll
        for (int k = 0; k < 4; ++k) {
            wmma::fragment<wmma::matrix_a, 16,16,16, __nv_bfloat16, wmma::row_major> A0, A1, A2;
            wmma::load_matrix_sync(A0, aQ + k*16, 72);
            wmma::load_matrix_sync(A1, aQ + 9216 + k*16, 72);
            wmma::load_matrix_sync(A2, aQ + 18432 + k*16, 72);
            wmma::fragment<wmma::matrix_b, 16,16,16, __nv_bfloat16, wmma::col_major> B0, B1;
            // B = hi: terms hh, mh, lh
            wmma::load_matrix_sync(B0, cb + k*16, 72);
            wmma::load_matrix_sync(B1, cb + 16*72 + k*16, 72);
            wmma::mma_sync(Cf0, A0, B0, Cf0);
            wmma::mma_sync(Cf1, A0, B1, Cf1);
            wmma::mma_sync(Cf0, A1, B0, Cf0);
            wmma::mma_sync(Cf1, A1, B1, Cf1);
            wmma::mma_sync(Cf0, A2, B0, Cf0);
            wmma::mma_sync(Cf1, A2, B1, Cf1);
            // B = mid: terms hm, mm
            wmma::load_matrix_sync(B0, cb + 2304 + k*16, 72);
            wmma::load_matrix_sync(B1, cb + 2304 + 16*72 + k*16, 72);
            wmma::mma_sync(Cf0, A0, B0, Cf0);
            wmma::mma_sync(Cf1, A0, B1, Cf1);
            wmma::mma_sync(Cf0, A1, B0, Cf0);
            wmma::mma_sync(Cf1, A1, B1, Cf1);
            // B = lo: term hl
            wmma::load_matrix_sync(B0, cb + 4608 + k*16, 72);
            wmma::load_matrix_sync(B1, cb + 4608 + 16*72 + k*16, 72);
            wmma::mma_sync(Cf0, A0, B0, Cf0);
            wmma::mma_sync(Cf1, A0, B1, Cf1);
        }
        wmma::store_matrix_sync(wd,      Cf0, 40, wmma::mem_row_major);
        wmma::store_matrix_sync(wd + 16, Cf1, 40, wmma::mem_row_major);
        __syncwarp();

        // ---- scan: 2 threads/query, 16 cands each; key = sqC - 2*dot ----
        const float* rowp = wd + qi*40 + hh*16;
        const float* sqb  = sqCs + buf*32 + hh*16;
        const int cbg = cbase + hh*16;
        #pragma unroll
        for (int g = 0; g < 4; ++g) {
            float4 dv = *(const float4*)(rowp + g*4);
            float d0 = fmaf(-2.f, dv.x, sqb[g*4+0]);
            float d1 = fmaf(-2.f, dv.y, sqb[g*4+1]);
            float d2 = fmaf(-2.f, dv.z, sqb[g*4+2]);
            float d3 = fmaf(-2.f, dv.w, sqb[g*4+3]);
            float mn = fminf(fminf(d0, d1), fminf(d2, d3));
            if (mn < listD[15]) {
                INS_STRICT(d0, cbg+g*4+0); INS_STRICT(d1, cbg+g*4+1);
                INS_STRICT(d2, cbg+g*4+2); INS_STRICT(d3, cbg+g*4+3);
            }
        }

        if (tile + 1 < 128) CP_WAIT0();
        __syncthreads();
    }

    // ---- merge the two 16-lists per query (reuse dead Q smem) ----
    float* mD = (float*)sm;
    int*   mI = (int*)(sm + 16384);
    const int q = w*16 + qi;
    #pragma unroll
    for (int e = 0; e < 16; ++e) {
        mD[q*32 + hh*16 + e] = listD[e];
        mI[q*32 + hh*16 + e] = listI[e];
    }
    __syncthreads();
    if (hh == 0) {
        #pragma unroll
        for (int e = 0; e < 16; ++e) {
            float dd = mD[q*32 + 16 + e];
            int   ci = mI[q*32 + 16 + e];
            if (dd < listD[15] || (dd == listD[15] && ci < listI[15])) {
                float cd = dd; int cix = ci;
                #pragma unroll
                for (int e2 = 0; e2 < 16; ++e2) {
                    bool bt = (cd < listD[e2]) || (cd == listD[e2] && cix < listI[e2]);
                    float od = listD[e2]; int oi = listI[e2];
                    if (bt) { listD[e2] = cd; listI[e2] = cix; cd = od; cix = oi; }
                }
            }
        }
        int gq = qbase + q;
        #pragma unroll
        for (int e = 0; e < 16; ++e) outIx[(size_t)gq*16 + e] = listI[e];
    }
}

// ---------------- L3: h = p_rel @ wp1 + bp1, plus partial stats (3 ch) ----------------
__global__ __launch_bounds__(256) void hstats_kernel(
    const float* __restrict__ p, const float* __restrict__ wp1, const float* __restrict__ bp1)
{
    int t = threadIdx.x;
    float w[9];
    #pragma unroll
    for (int j = 0; j < 9; ++j) w[j] = wp1[j];
    float b0 = bp1[0], b1 = bp1[1], b2 = bp1[2];
    float s0=0,s1=0,s2=0,q0=0,q1=0,q2=0;
    for (int rep = 0; rep < 4; ++rep) {
        int row = blockIdx.x*1024 + rep*256 + t;
        int n = row >> 4;
        int gi = d_idxk[row];
        float r0 = p[(size_t)gi*3+0] - p[(size_t)n*3+0];
        float r1 = p[(size_t)gi*3+1] - p[(size_t)n*3+1];
        float r2 = p[(size_t)gi*3+2] - p[(size_t)n*3+2];
        float h0 = r0*w[0] + r1*w[3] + r2*w[6] + b0;
        float h1 = r0*w[1] + r1*w[4] + r2*w[7] + b1;
        float h2 = r0*w[2] + r1*w[5] + r2*w[8] + b2;
        d_h[(size_t)row*3+0] = h0; d_h[(size_t)row*3+1] = h1; d_h[(size_t)row*3+2] = h2;
        s0 += h0; s1 += h1; s2 += h2;
        q0 += h0*h0; q1 += h1*h1; q2 += h2*h2;
    }
    __shared__ float red[6][256];
    red[0][t]=s0; red[1][t]=s1; red[2][t]=s2; red[3][t]=q0; red[4][t]=q1; red[5][t]=q2;
    __syncthreads();
    for (int st = 128; st; st >>= 1) {
        if (t < st) {
            #pragma unroll
            for (int e = 0; e < 6; ++e) red[e][t] += red[e][t+st];
        }
        __syncthreads();
    }
    if (t < 6) d_part[blockIdx.x*6 + t] = red[t][0];
}

// ---------------- generic deterministic finalize (mean / rstd) ----------------
__global__ __launch_bounds__(256) void finalize_kernel(int nch, int nblocks, int statOff)
{
    __shared__ double sh[512];
    int t = threadIdx.x;
    int nsl = 256 / nch;
    int c = t % nch, sl = t / nch;
    double s = 0.0, q = 0.0;
    if (sl < nsl) {
        for (int b = sl; b < nblocks; b += nsl) {
            s += (double)d_part[(size_t)b*2*nch + c];
            q += (double)d_part[(size_t)b*2*nch + nch + c];
        }
    }
    sh[t] = s; sh[256 + t] = q;
    __syncthreads();
    if (t < nch) {
        double S = 0.0, Q = 0.0;
        for (int s2 = 0; s2 < nsl; ++s2) { S += sh[s2*nch + t]; Q += sh[256 + s2*nch + t]; }
        double cnt = (double)NKROWS;
        double m = S / cnt;
        double v = Q / cnt - m*m;
        d_stats[statOff + t]        = (float)m;
        d_stats[statOff + nch + t]  = (float)(1.0 / sqrt(v + 1e-5));
    }
}

// ---------------- L5: r = xk_g - xq + p_r, plus partial stats over r (64 ch) -----
__global__ __launch_bounds__(256) void r_kernel(
    const float* __restrict__ gp, const float* __restrict__ btp,
    const float* __restrict__ wp2, const float* __restrict__ bp2)
{
    int t = threadIdx.x;
    int rl = t >> 4, quad = t & 15;
    __shared__ float wp2s[3][64];
    __shared__ float bp2s[64];
    __shared__ float bnp[12];
    if (t < 192) wp2s[t/64][t%64] = wp2[t];
    if (t < 64)  bp2s[t] = bp2[t];
    if (t < 6)   bnp[t] = d_stats[t];
    if (t >= 6 && t < 9)   bnp[t] = gp[t-6];
    if (t >= 9 && t < 12)  bnp[t] = btp[t-9];
    __syncthreads();

    float4 w0 = *(const float4*)&wp2s[0][quad*4];
    float4 w1 = *(const float4*)&wp2s[1][quad*4];
    float4 w2 = *(const float4*)&wp2s[2][quad*4];
    float4 bp4 = *(const float4*)&bp2s[quad*4];
    float sx=0,sy=0,sz=0,sw=0, qx=0,qy=0,qz=0,qw=0;

    for (int it = 0; it < 32; ++it) {
        size_t row = (size_t)blockIdx.x*512 + it*16 + rl;
        float h0 = d_h[row*3+0], h1 = d_h[row*3+1], h2 = d_h[row*3+2];
        h0 = fmaxf((h0 - bnp[0])*bnp[3]*bnp[6] + bnp[9],  0.f);
        h1 = fmaxf((h1 - bnp[1])*bnp[4]*bnp[7] + bnp[10], 0.f);
        h2 = fmaxf((h2 - bnp[2])*bnp[5]*bnp[8] + bnp[11], 0.f);
        float4 pr;
        pr.x = bp4.x + h0*w0.x + h1*w1.x + h2*w2.x;
        pr.y = bp4.y + h0*w0.y + h1*w1.y + h2*w2.y;
        pr.z = bp4.z + h0*w0.z + h1*w1.z + h2*w2.z;
        pr.w = bp4.w + h0*w0.w + h1*w1.w + h2*w2.w;
        int n  = (int)(row >> 4);
        int gi = d_idxk[row];
        float4 xk4 = *(const float4*)&d_xk[(size_t)gi*64 + quad*4];
        float4 xq4 = *(const float4*)&d_xq[(size_t)n*64 + quad*4];
        float4 r4;
        r4.x = xk4.x - xq4.x + pr.x;
        r4.y = xk4.y - xq4.y + pr.y;
        r4.z = xk4.z - xq4.z + pr.z;
        r4.w = xk4.w - xq4.w + pr.w;
        *(float4*)&d_rr[row*64 + quad*4] = r4;
        sx += r4.x; sy += r4.y; sz += r4.z; sw += r4.w;
        qx += r4.x*r4.x; qy += r4.y*r4.y; qz += r4.z*r4.z; qw += r4.w*r4.w;
    }
    __shared__ float red[16][16][8];
    red[rl][quad][0]=sx; red[rl][quad][1]=sy; red[rl][quad][2]=sz; red[rl][quad][3]=sw;
    red[rl][quad][4]=qx; red[rl][quad][5]=qy; red[rl][quad][6]=qz; red[rl][quad][7]=qw;
    __syncthreads();
    for (int st = 8; st; st >>= 1) {
        if (rl < st) {
            #pragma unroll
            for (int e = 0; e < 8; ++e) red[rl][quad][e] += red[rl+st][quad][e];
        }
        __syncthreads();
    }
    if (rl == 0) {
        #pragma unroll
        for (int j = 0; j < 4; ++j) {
            d_part[(size_t)blockIdx.x*128 + quad*4 + j]      = red[0][quad][j];
            d_part[(size_t)blockIdx.x*128 + 64 + quad*4 + j] = red[0][quad][4+j];
        }
    }
}

// ---------------- L7: w1 = relu(bn1(r)) @ ww1 + bw1, plus partial stats (8 ch) ----------------
__global__ __launch_bounds__(256) void w1_kernel(
    const float* __restrict__ g1, const float* __restrict__ bt1,
    const float* __restrict__ ww1, const float* __restrict__ bw1)
{
    int t = threadIdx.x;
    int rw = t >> 3, j = t & 7;
    __shared__ float rS[32][65];
    __shared__ float ww1s[64][8];
    __shared__ float bn1[256];
    __shared__ float bw1s[8];
    if (t < 64) {
        bn1[t]       = d_stats[8 + t];
        bn1[64 + t]  = d_stats[72 + t];
        bn1[128 + t] = g1[t];
        bn1[192 + t] = bt1[t];
    }
    if (t < 8) bw1s[t] = bw1[t];
    for (int i = t; i < 512; i += 256) ww1s[i>>3][i&7] = ww1[i];
    __syncthreads();

    float sj = 0.f, qj = 0.f;
    for (int it = 0; it < 16; ++it) {
        size_t rowbase = (size_t)blockIdx.x*512 + it*32;
        __syncthreads();
        for (int i = t; i < 2048; i += 256) {
            int r = i >> 6, c = i & 63;
            float v = d_rr[(rowbase + r)*64 + c];
            v = fmaxf((v - bn1[c])*bn1[64+c]*bn1[128+c] + bn1[192+c], 0.f);
            rS[r][c] = v;
        }
        __syncthreads();
        float acc = bw1s[j];
        #pragma unroll 8
        for (int c = 0; c < 64; ++c) acc += rS[rw][c] * ww1s[c][j];
        d_w1[(rowbase + rw)*8 + j] = acc;
        sj += acc; qj += acc*acc;
    }
    __shared__ float red2[32][8][2];
    red2[rw][j][0] = sj; red2[rw][j][1] = qj;
    __syncthreads();
    for (int st = 16; st; st >>= 1) {
        if (rw < st) {
            red2[rw][j][0] += red2[rw+st][j][0];
            red2[rw][j][1] += red2[rw+st][j][1];
        }
        __syncthreads();
    }
    if (rw == 0) {
        d_part[(size_t)blockIdx.x*16 + j]     = red2[0][j][0];
        d_part[(size_t)blockIdx.x*16 + 8 + j] = red2[0][j][1];
    }
}

// ---------------- L9: w2, softmax, combine (p_r recomputed from d_h) ----------
__global__ __launch_bounds__(256) void final_kernel(
    const float* __restrict__ g2, const float* __restrict__ bt2,
    const float* __restrict__ ww2, const float* __restrict__ bw2,
    const float* __restrict__ gp, const float* __restrict__ btp,
    const float* __restrict__ wp2, const float* __restrict__ bp2,
    float* __restrict__ out)
{
    int t = threadIdx.x, w = t >> 5, l = t & 31;
    int n = blockIdx.x*8 + w;
    __shared__ float ww2s[64];
    __shared__ float prm[32];
    __shared__ float bw2s[8];
    __shared__ float wsh[8][16][8];
    __shared__ float inv[8][8];
    __shared__ float wp2s[3][64];
    __shared__ float bp2s[64];
    __shared__ float bnp[12];
    if (t < 64) ww2s[t] = ww2[t];
    if (t < 8) {
        prm[t]      = d_stats[136 + t];
        prm[8 + t]  = d_stats[144 + t];
        prm[16 + t] = g2[t];
        prm[24 + t] = bt2[t];
        bw2s[t]     = bw2[t];
    }
    if (t >= 64 && t < 256) wp2s[(t-64)/64][(t-64)%64] = wp2[t-64];
    if (t >= 8 && t < 72) bp2s[t-8] = bp2[t-8];
    if (t >= 72 && t < 78)  bnp[t-72] = d_stats[t-72];
    if (t >= 78 && t < 81)  bnp[t-72] = gp[t-78];
    if (t >= 81 && t < 84)  bnp[t-72] = btp[t-81];
    __syncthreads();

    #pragma unroll
    for (int rep = 0; rep < 4; ++rep) {
        int e = rep*32 + l;
        int tt = e >> 3, j = e & 7;
        const float* w1row = &d_w1[((size_t)n*16 + tt)*8];
        float acc = bw2s[j];
        #pragma unroll
        for (int c = 0; c < 8; ++c) {
            float v = fmaxf((w1row[c] - prm[c])*prm[8+c]*prm[16+c] + prm[24+c], 0.f);
            acc += v * ww2s[c*8 + j];
        }
        wsh[w][tt][j] = acc;
    }
    __syncwarp();
    if (l < 8) {
        float m = -3.4e38f;
        #pragma unroll
        for (int tt = 0; tt < 16; ++tt) m = fmaxf(m, wsh[w][tt][l]);
        float ssum = 0.f;
        #pragma unroll
        for (int tt = 0; tt < 16; ++tt) {
            float e_ = expf(wsh[w][tt][l] - m);
            wsh[w][tt][l] = e_;
            ssum += e_;
        }
        inv[w][l] = 1.f / ssum;
    }
    __syncwarp();
    int j = l & 7;
    float acc0 = 0.f, acc1 = 0.f;
    const int* idxr = &d_idxv[(size_t)n*16];
    #pragma unroll
    for (int tt = 0; tt < 16; ++tt) {
        int gi = idxr[tt];
        float wt = wsh[w][tt][j];
        size_t row = (size_t)n*16 + tt;
        float h0 = d_h[row*3+0], h1 = d_h[row*3+1], h2 = d_h[row*3+2];
        h0 = fmaxf((h0 - bnp[0])*bnp[3]*bnp[6] + bnp[9],  0.f);
        h1 = fmaxf((h1 - bnp[1])*bnp[4]*bnp[7] + bnp[10], 0.f);
        h2 = fmaxf((h2 - bnp[2])*bnp[5]*bnp[8] + bnp[11], 0.f);
        float pr0 = bp2s[l]    + h0*wp2s[0][l]    + h1*wp2s[1][l]    + h2*wp2s[2][l];
        float pr1 = bp2s[32+l] + h0*wp2s[0][32+l] + h1*wp2s[1][32+l] + h2*wp2s[2][32+l];
        acc0 += (d_xv[(size_t)gi*64 + l]      + pr0) * wt;
        acc1 += (d_xv[(size_t)gi*64 + 32 + l] + pr1) * wt;
    }
    float iv = inv[w][j];
    out[(size_t)n*64 + l]      = acc0 * iv;
    out[(size_t)n*64 + 32 + l] = acc1 * iv;
}

// ---------------- launch ----------------
extern "C" void kernel_launch(void* const* d_in, const int* in_sizes, int n_in,
                              void* d_out, int out_size)
{
    const float* p   = (const float*)d_in[0];
    const float* x   = (const float*)d_in[1];
    // d_in[2] = o (batch sizes, structurally fixed -> unused)
    const float* wq  = (const float*)d_in[3];  const float* bq  = (const float*)d_in[4];
    const float* wk  = (const float*)d_in[5];  const float* bk  = (const float*)d_in[6];
    const float* wv  = (const float*)d_in[7];  const float* bv  = (const float*)d_in[8];
    const float* wp1 = (const float*)d_in[9];  const float* bp1 = (const float*)d_in[10];
    const float* gp  = (const float*)d_in[11]; const float* btp = (const float*)d_in[12];
    const float* wp2 = (const float*)d_in[13]; const float* bp2 = (const float*)d_in[14];
    const float* g1  = (const float*)d_in[15]; const float* bt1 = (const float*)d_in[16];
    const float* ww1 = (const float*)d_in[17]; const float* bw1 = (const float*)d_in[18];
    const float* g2  = (const float*)d_in[19]; const float* bt2 = (const float*)d_in[20];
    const float* ww2 = (const float*)d_in[21]; const float* bw2 = (const float*)d_in[22];
    float* out = (float*)d_out;

    cudaFuncSetAttribute(knn_kernel, cudaFuncAttributeMaxDynamicSharedMemorySize,
                         KNN_SMEM_BYTES);

    qkv_kernel<<<2048, 256>>>(x, wq, bq, wk, bk, wv, bv);   // launch 1
    split_kernel<<<4096, 256>>>();                          // launch 2
    noop_kernel<<<1, 32>>>();                               // launch 3 (ncu alignment)
    dim3 kg(32, 8, 2);
    knn_kernel<<<kg, 256, KNN_SMEM_BYTES>>>();              // launch 4 <- profiled
    hstats_kernel<<<512, 256>>>(p, wp1, bp1);
    finalize_kernel<<<1, 256>>>(3, 512, 0);
    r_kernel<<<1024, 256>>>(gp, btp, wp2, bp2);
    finalize_kernel<<<1, 256>>>(64, 1024, 8);
    w1_kernel<<<1024, 256>>>(g1, bt1, ww1, bw1);
    finalize_kernel<<<1, 256>>>(8, 1024, 136);
    final_kernel<<<4096, 256>>>(g2, bt2, ww2, bw2, gp, btp, wp2, bp2, out);
}